// round 11
// baseline (speedup 1.0000x reference)
#include <cuda_runtime.h>
#include <cuda_bf16.h>
#include <mma.h>
#include <cstdint>

using namespace nvcuda;

// Problem constants
#define BATCH  4
#define SEQ    4096
#define DMODEL 1024
#define NHEAD  16
#define HDIM   64
#define DFF    4096
#define WIN    512
#define MROWS  (BATCH*SEQ)          // 16384

// ---------------- scratch (device globals; no allocations allowed) ----------
static __device__ float g_attn[(size_t)MROWS * DMODEL];
static __device__ float g_xln [(size_t)MROWS * DMODEL];
static __device__ float g_y   [(size_t)MROWS * DMODEL];
// bf16 split planes (hi/lo)
static __device__ __align__(16) __nv_bfloat16 g_srch[(size_t)MROWS * DMODEL];
static __device__ __align__(16) __nv_bfloat16 g_srcl[(size_t)MROWS * DMODEL];
static __device__ __align__(16) __nv_bfloat16 g_wqkvh[(size_t)3 * DMODEL * DMODEL];
static __device__ __align__(16) __nv_bfloat16 g_wqkvl[(size_t)3 * DMODEL * DMODEL];
static __device__ __align__(16) __nv_bfloat16 g_w1h[(size_t)DFF * DMODEL];
static __device__ __align__(16) __nv_bfloat16 g_w1l[(size_t)DFF * DMODEL];
static __device__ __align__(16) __nv_bfloat16 g_w2h[(size_t)DMODEL * DFF];
static __device__ __align__(16) __nv_bfloat16 g_w2l[(size_t)DMODEL * DFF];
static __device__ __align__(16) __nv_bfloat16 g_xh [(size_t)MROWS * DMODEL];
static __device__ __align__(16) __nv_bfloat16 g_xl [(size_t)MROWS * DMODEL];
static __device__ __align__(16) __nv_bfloat16 g_hh [(size_t)MROWS * DFF];
static __device__ __align__(16) __nv_bfloat16 g_hl [(size_t)MROWS * DFF];
// q/k/v split planes, [3][B,H,S,d] hi and lo
static __device__ __align__(16) __nv_bfloat16 g_qkvh[(size_t)3 * MROWS * DMODEL];
static __device__ __align__(16) __nv_bfloat16 g_qkvl[(size_t)3 * MROWS * DMODEL];
static __device__ float g_bqkv[3 * DMODEL];

__device__ __forceinline__ void cp16(void* dst, const void* src) {
    unsigned int d = (unsigned int)__cvta_generic_to_shared(dst);
    asm volatile("cp.async.cg.shared.global [%0], [%1], 16;\n" :: "r"(d), "l"(src));
}

// split 4 fp32 values into bf16 hi/lo planes (8B store each)
__device__ __forceinline__ void split_store4(float4 x, __nv_bfloat16* hp, __nv_bfloat16* lp) {
    __nv_bfloat16 h0 = __float2bfloat16(x.x);
    __nv_bfloat16 h1 = __float2bfloat16(x.y);
    __nv_bfloat16 h2 = __float2bfloat16(x.z);
    __nv_bfloat16 h3 = __float2bfloat16(x.w);
    __nv_bfloat16 l0 = __float2bfloat16(x.x - __bfloat162float(h0));
    __nv_bfloat16 l1 = __float2bfloat16(x.y - __bfloat162float(h1));
    __nv_bfloat16 l2 = __float2bfloat16(x.z - __bfloat162float(h2));
    __nv_bfloat16 l3 = __float2bfloat16(x.w - __bfloat162float(h3));
    ((__nv_bfloat162*)hp)[0] = __nv_bfloat162(h0, h1);
    ((__nv_bfloat162*)hp)[1] = __nv_bfloat162(h2, h3);
    ((__nv_bfloat162*)lp)[0] = __nv_bfloat162(l0, l1);
    ((__nv_bfloat162*)lp)[1] = __nv_bfloat162(l2, l3);
}

// ============================================================================
// Fused prepass: split src + {wq,wk,wv}->wqkv + w1 + w2 into bf16 hi/lo,
// pack {bq,bk,bv}->bqkv (fp32). Indices are float4 groups.
// ============================================================================
#define RA_TOTAL 7078656
__global__ __launch_bounds__(256)
void round_all(const float* __restrict__ src,
               const float* __restrict__ wq, const float* __restrict__ wk,
               const float* __restrict__ wv, const float* __restrict__ w1,
               const float* __restrict__ w2, const float* __restrict__ bq,
               const float* __restrict__ bk, const float* __restrict__ bv,
               __nv_bfloat16* __restrict__ srch, __nv_bfloat16* __restrict__ srcl,
               __nv_bfloat16* __restrict__ wqkvh, __nv_bfloat16* __restrict__ wqkvl,
               __nv_bfloat16* __restrict__ w1h, __nv_bfloat16* __restrict__ w1l,
               __nv_bfloat16* __restrict__ w2h, __nv_bfloat16* __restrict__ w2l,
               float* __restrict__ bqkv)
{
    long long i = (long long)blockIdx.x * 256 + threadIdx.x;
    if (i >= RA_TOTAL) return;
    if (i >= 7077888) {                 // bias pack, fp32 copy
        long long j = i - 7077888;      // 0..767
        const float* in;
        float* op;
        if (j < 256)      { in = bq + j * 4;         op = bqkv + j * 4; }
        else if (j < 512) { in = bk + (j - 256) * 4; op = bqkv + 1024 + (j - 256) * 4; }
        else              { in = bv + (j - 512) * 4; op = bqkv + 2048 + (j - 512) * 4; }
        *(float4*)op = *(const float4*)in;
        return;
    }
    const float* in;
    __nv_bfloat16 *hp, *lp;
    if (i < 4194304)      { in = src + i * 4; hp = srch + i * 4; lp = srcl + i * 4; }
    else if (i < 4456448) { long long j = i - 4194304; in = wq + j * 4; hp = wqkvh + j * 4; lp = wqkvl + j * 4; }
    else if (i < 4718592) { long long j = i - 4456448; in = wk + j * 4; hp = wqkvh + 1048576 + j * 4; lp = wqkvl + 1048576 + j * 4; }
    else if (i < 4980736) { long long j = i - 4718592; in = wv + j * 4; hp = wqkvh + 2097152 + j * 4; lp = wqkvl + 2097152 + j * 4; }
    else if (i < 6029312) { long long j = i - 4980736; in = w1 + j * 4; hp = w1h + j * 4; lp = w1l + j * 4; }
    else                  { long long j = i - 6029312; in = w2 + j * 4; hp = w2h + j * 4; lp = w2l + j * 4; }
    split_store4(*(const float4*)in, hp, lp);
}

// ============================================================================
// Split-bf16 TN GEMM: C = (Ah+Al)(Wh+Wl)^T ~= Ah Wh^T + Al Wh^T + Ah Wl^T
// Block 128x128, BK=32, 256 thr = 8 warps as 4(m:32-row) x 2(n:64-col);
// warp tile 32x64 via m16n16k16 bf16 wmma (ldmatrix operand path).
//   MODE 0: +bias(packed), split-store QKV -> qkvh/qkvl planes [3][B,H,S,d]
//   MODE 1: +bias, ReLU, write bf16 split pair (FFN1)
//   MODE 2: +bias, +extra fp32 residual, fp32 out (FFN2)
// ============================================================================
#define BM 128
#define BN 128
#define BK 32
#define LDB 40                       // bf16 elems per row (80B) - LDSM conflict-free
#define PLANE (128 * LDB)            // 5120 bf16
#define STG (4 * PLANE)              // Ah|Al|Bh|Bl per stage = 20480 bf16 = 40960 B
#define SPLIT_SMEM (2 * STG * (int)sizeof(__nv_bfloat16))   // 81920 B
#define QKV_PLANE ((size_t)MROWS * DMODEL)

template <int MODE>
__global__ __launch_bounds__(256, 2)
void gemm_split(const __nv_bfloat16* __restrict__ Ah, const __nv_bfloat16* __restrict__ Al,
                const __nv_bfloat16* __restrict__ Wh, const __nv_bfloat16* __restrict__ Wl,
                const float* __restrict__ bias, const float* __restrict__ extra,
                float* __restrict__ out0,
                __nv_bfloat16* __restrict__ oh, __nv_bfloat16* __restrict__ ol,
                int K, int N)
{
    extern __shared__ __nv_bfloat16 smp[];
    const int tid = threadIdx.x;
    const int wid = tid >> 5;
    const int lane = tid & 31;
    const int wm = wid & 3;      // 0..3 (32-row strips)
    const int wn = wid >> 2;     // 0..1 (64-col strips)

    wmma::fragment<wmma::accumulator, 16, 16, 16, float> acc[2][4];
#pragma unroll
    for (int i = 0; i < 2; i++)
#pragma unroll
        for (int j = 0; j < 4; j++)
            wmma::fill_fragment(acc[i][j], 0.0f);

    const __nv_bfloat16* Ahg = Ah + (size_t)blockIdx.y * BM * K;
    const __nv_bfloat16* Alg = Al + (size_t)blockIdx.y * BM * K;
    const __nv_bfloat16* Whg = Wh + (size_t)blockIdx.x * BN * K;
    const __nv_bfloat16* Wlg = Wl + (size_t)blockIdx.x * BN * K;

    auto load_stage = [&](int s, int kt) {
        __nv_bfloat16* st = smp + s * STG;
#pragma unroll
        for (int p = 0; p < 2; p++) {
            int c = tid + p * 256;            // 0..511
            int r = c >> 2, col = (c & 3) * 8;
            size_t go = (size_t)r * K + kt + col;
            unsigned so = r * LDB + col;
            cp16(st + so,             Ahg + go);
            cp16(st + PLANE + so,     Alg + go);
            cp16(st + 2 * PLANE + so, Whg + go);
            cp16(st + 3 * PLANE + so, Wlg + go);
        }
        asm volatile("cp.async.commit_group;\n");
    };

    const int T = K / BK;
    load_stage(0, 0);

    for (int t = 0; t < T; t++) {
        const int cur = t & 1;
        if (t + 1 < T) {
            load_stage(cur ^ 1, (t + 1) * BK);
            asm volatile("cp.async.wait_group 1;\n");
        } else {
            asm volatile("cp.async.wait_group 0;\n");
        }
        __syncthreads();

        const __nv_bfloat16* Ahs = smp + cur * STG;
        const __nv_bfloat16* Als = Ahs + PLANE;
        const __nv_bfloat16* Bhs = Ahs + 2 * PLANE;
        const __nv_bfloat16* Bls = Ahs + 3 * PLANE;

#pragma unroll
        for (int kk = 0; kk < BK; kk += 16) {
            wmma::fragment<wmma::matrix_a, 16, 16, 16, __nv_bfloat16, wmma::row_major> ah[2], al[2];
#pragma unroll
            for (int i = 0; i < 2; i++) {
                wmma::load_matrix_sync(ah[i], Ahs + (wm * 32 + i * 16) * LDB + kk, LDB);
                wmma::load_matrix_sync(al[i], Als + (wm * 32 + i * 16) * LDB + kk, LDB);
            }
#pragma unroll
            for (int j = 0; j < 4; j++) {
                wmma::fragment<wmma::matrix_b, 16, 16, 16, __nv_bfloat16, wmma::col_major> bh, bl;
                wmma::load_matrix_sync(bh, Bhs + (wn * 64 + j * 16) * LDB + kk, LDB);
                wmma::load_matrix_sync(bl, Bls + (wn * 64 + j * 16) * LDB + kk, LDB);
#pragma unroll
                for (int i = 0; i < 2; i++) {
                    wmma::mma_sync(acc[i][j], ah[i], bh, acc[i][j]);
                    wmma::mma_sync(acc[i][j], al[i], bh, acc[i][j]);
                    wmma::mma_sync(acc[i][j], ah[i], bl, acc[i][j]);
                }
            }
        }
        __syncthreads();
    }

    // Per-warp epilogue staging: 32x64 fp32 strip, stride 68.
    float* Cw = (float*)smp + wid * (32 * 68);
#pragma unroll
    for (int i = 0; i < 2; i++)
#pragma unroll
        for (int j = 0; j < 4; j++)
            wmma::store_matrix_sync(Cw + (i * 16) * 68 + j * 16, acc[i][j], 68,
                                    wmma::mem_row_major);
    __syncwarp();

    const int m = blockIdx.y * BM + wm * 32 + lane;
    const int n0 = blockIdx.x * BN + wn * 64;
    const float* crow = Cw + lane * 68;

#pragma unroll
    for (int c4 = 0; c4 < 16; c4++) {
        int n = n0 + c4 * 4;
        float4 c = *(float4*)(crow + c4 * 4);
        float4 bb = *(const float4*)(bias + n);
        c.x += bb.x; c.y += bb.y; c.z += bb.z; c.w += bb.w;
        if constexpr (MODE == 1) {
            c.x = fmaxf(c.x, 0.f); c.y = fmaxf(c.y, 0.f);
            c.z = fmaxf(c.z, 0.f); c.w = fmaxf(c.w, 0.f);
            split_store4(c, oh + (size_t)m * N + n, ol + (size_t)m * N + n);
        } else if constexpr (MODE == 2) {
            float4 e = *(const float4*)(extra + (size_t)m * N + n);
            c.x += e.x; c.y += e.y; c.z += e.z; c.w += e.w;
            *(float4*)(out0 + (size_t)m * N + n) = c;
        } else {
            int mat = n >> 10;
            int nl  = n & 1023;
            int h   = nl >> 6;
            int dd  = nl & (HDIM - 1);
            int bi  = m >> 12;
            int s   = m & (SEQ - 1);
            size_t o = (((size_t)bi * NHEAD + h) * SEQ + s) * HDIM + dd;
            split_store4(c, oh + mat * QKV_PLANE + o, ol + mat * QKV_PLANE + o);
        }
    }
}

// ============================================================================
// Windowed causal flash attention, bf16x3:
// q/k/v read as pre-split bf16 hi/lo planes; QK^T and PV are 3-term bf16
// m16n16k16 wmma (LDSM operand path); P split at softmax store.
// Block = (b, h, 64-row q chunk), 256 thr = 8 warps as 2(m:32) x 4(n:16).
// ============================================================================
#define AQLD 72                     // bf16 row stride (144B, conflict-free LDSM)
#define APLANE (64 * AQLD)          // 4608 bf16
#define SLD 68                      // fp32 stride for S and acc
#define ATTN_SMEM (8 * APLANE * 2 + 2 * 64 * SLD * 4 + 2 * 64 * 4)  // 109056 B

__global__ __launch_bounds__(256, 2)
void attn_kernel(const __nv_bfloat16* __restrict__ qkvh,
                 const __nv_bfloat16* __restrict__ qkvl,
                 float* __restrict__ out)
{
    const int idx = blockIdx.x;
    const int qc = idx & 7;
    const int w  = (idx >> 3) & 7;
    const int h  = (idx >> 6) & 15;
    const int b  = idx >> 10;

    extern __shared__ char smc[];
    __nv_bfloat16* qh = (__nv_bfloat16*)smc;
    __nv_bfloat16* ql = qh + APLANE;
    __nv_bfloat16* kh = qh + 2 * APLANE;
    __nv_bfloat16* kl = qh + 3 * APLANE;
    __nv_bfloat16* vh = qh + 4 * APLANE;
    __nv_bfloat16* vl = qh + 5 * APLANE;
    __nv_bfloat16* ph = qh + 6 * APLANE;
    __nv_bfloat16* pl = qh + 7 * APLANE;
    float* s_s  = (float*)(smc + 8 * APLANE * 2);
    float* accs = s_s + 64 * SLD;
    float* m_s  = accs + 64 * SLD;
    float* l_s  = m_s + 64;

    const int tid = threadIdx.x;
    const int wid = tid >> 5;
    const int wm  = wid & 1;    // 0..1 (32-row strips)
    const int wn  = wid >> 1;   // 0..3 (16-col strips)
    const size_t NM = QKV_PLANE;
    const size_t headbase = ((size_t)(b * NHEAD + h)) * SEQ * HDIM;
    const int q0 = w * WIN + qc * 64;

    const int tr = tid >> 4;           // 0..15
    const int tc = (tid & 15) << 2;    // 0..60 step 4

    // load q hi/lo planes (64 rows x 64 bf16 = 512 uint4 chunks per plane)
    {
        const __nv_bfloat16* qgh = qkvh + headbase + (size_t)q0 * HDIM;
        const __nv_bfloat16* qgl = qkvl + headbase + (size_t)q0 * HDIM;
#pragma unroll
        for (int p = 0; p < 4; p++) {
            int c = tid + p * 256;          // 0..1023
            int plane = c >> 9;
            int cc = c & 511;
            int r = cc >> 3, col = (cc & 7) * 8;
            const __nv_bfloat16* s = (plane ? qgl : qgh) + (size_t)r * HDIM + col;
            __nv_bfloat16* d = (plane ? ql : qh) + r * AQLD + col;
            *(uint4*)d = *(const uint4*)s;
        }
    }
#pragma unroll
    for (int p = 0; p < 4; p++) {
        int r = tr + p * 16;
        *(float4*)(accs + r * SLD + tc) = make_float4(0.f, 0.f, 0.f, 0.f);
    }
    if (tid < 64) { m_s[tid] = -1e30f; l_s[tid] = 0.f; }

    const int kstart = (w == 0) ? 0 : (w - 1) * WIN;
    const int kend   = q0 + 64;

    const __nv_bfloat16* kgh = qkvh + NM + headbase;
    const __nv_bfloat16* kgl = qkvl + NM + headbase;
    const __nv_bfloat16* vgh = qkvh + 2 * NM + headbase;
    const __nv_bfloat16* vgl = qkvl + 2 * NM + headbase;

    for (int kc = kstart; kc < kend; kc += 64) {
        __syncthreads();   // prev PV complete before overwriting k/v planes

        // load k/v hi/lo planes (4 planes x 512 chunks)
#pragma unroll
        for (int p = 0; p < 8; p++) {
            int c = tid + p * 256;          // 0..2047
            int plane = c >> 9;             // 0:kh 1:kl 2:vh 3:vl
            int cc = c & 511;
            int r = cc >> 3, col = (cc & 7) * 8;
            const __nv_bfloat16* s =
                (plane == 0 ? kgh : plane == 1 ? kgl : plane == 2 ? vgh : vgl)
                + (size_t)(kc + r) * HDIM + col;
            __nv_bfloat16* d =
                (plane == 0 ? kh : plane == 1 ? kl : plane == 2 ? vh : vl)
                + r * AQLD + col;
            *(uint4*)d = *(const uint4*)s;
        }
        __syncthreads();   // k/v ready

        // S = q @ K^T (3-term bf16)
        {
            wmma::fragment<wmma::accumulator, 16, 16, 16, float> sacc[2];
#pragma unroll
            for (int i = 0; i < 2; i++) wmma::fill_fragment(sacc[i], 0.0f);
#pragma unroll
            for (int ks = 0; ks < 4; ks++) {
                wmma::fragment<wmma::matrix_b, 16, 16, 16, __nv_bfloat16, wmma::col_major> bh, bl;
                wmma::load_matrix_sync(bh, kh + (wn * 16) * AQLD + ks * 16, AQLD);
                wmma::load_matrix_sync(bl, kl + (wn * 16) * AQLD + ks * 16, AQLD);
#pragma unroll
                for (int i = 0; i < 2; i++) {
                    wmma::fragment<wmma::matrix_a, 16, 16, 16, __nv_bfloat16, wmma::row_major> ah, al;
                    wmma::load_matrix_sync(ah, qh + (wm * 32 + i * 16) * AQLD + ks * 16, AQLD);
                    wmma::load_matrix_sync(al, ql + (wm * 32 + i * 16) * AQLD + ks * 16, AQLD);
                    wmma::mma_sync(sacc[i], ah, bh, sacc[i]);
                    wmma::mma_sync(sacc[i], al, bh, sacc[i]);
                    wmma::mma_sync(sacc[i], ah, bl, sacc[i]);
                }
            }
#pragma unroll
            for (int i = 0; i < 2; i++)
                wmma::store_matrix_sync(s_s + (wm * 32 + i * 16) * SLD + wn * 16,
                                        sacc[i], SLD, wmma::mem_row_major);
        }
        __syncthreads();   // scores ready

        // online softmax (scale 1/8 applied here); P split-stored to ph/pl
        {
            const bool diag = (kc == q0);
            const int r  = tid >> 2;           // 0..63
            const int c0 = (tid & 3) << 4;     // 0,16,32,48
            float* srow = s_s + r * SLD + c0;
            float sv[16];
            float mloc = -1e30f;
#pragma unroll
            for (int t = 0; t < 16; t++) {
                float x = srow[t] * 0.125f;
                if (diag && (c0 + t > r)) x = -1e30f;
                sv[t] = x;
                mloc = fmaxf(mloc, x);
            }
            mloc = fmaxf(mloc, __shfl_xor_sync(0xffffffffu, mloc, 1));
            mloc = fmaxf(mloc, __shfl_xor_sync(0xffffffffu, mloc, 2));
            float mold = m_s[r];
            float mnew = fmaxf(mold, mloc);
            float ssum = 0.f;
#pragma unroll
            for (int t = 0; t < 16; t += 2) {
                float p0 = __expf(sv[t]     - mnew);
                float p1 = __expf(sv[t + 1] - mnew);
                ssum += p0 + p1;
                __nv_bfloat16 h0 = __float2bfloat16(p0);
                __nv_bfloat16 h1 = __float2bfloat16(p1);
                __nv_bfloat16 l0 = __float2bfloat16(p0 - __bfloat162float(h0));
                __nv_bfloat16 l1 = __float2bfloat16(p1 - __bfloat162float(h1));
                *(__nv_bfloat162*)(ph + r * AQLD + c0 + t) = __nv_bfloat162(h0, h1);
                *(__nv_bfloat162*)(pl + r * AQLD + c0 + t) = __nv_bfloat162(l0, l1);
            }
            ssum += __shfl_xor_sync(0xffffffffu, ssum, 1);
            ssum += __shfl_xor_sync(0xffffffffu, ssum, 2);
            float alpha = __expf(mold - mnew);   // 0 on first chunk
            if ((tid & 3) == 0) {
                m_s[r] = mnew;
                l_s[r] = l_s[r] * alpha + ssum;
            }
            // rescale accumulator rows in-place
            float* arow = accs + r * SLD + c0;
#pragma unroll
            for (int t = 0; t < 4; t++) {
                float4 a4 = *(float4*)(arow + t * 4);
                a4.x *= alpha; a4.y *= alpha; a4.z *= alpha; a4.w *= alpha;
                *(float4*)(arow + t * 4) = a4;
            }
        }
        __syncthreads();   // P planes + scaled accs ready

        // accs += P @ V (3-term bf16), accumulate in place
        {
            wmma::fragment<wmma::accumulator, 16, 16, 16, float> oacc[2];
#pragma unroll
            for (int i = 0; i < 2; i++)
                wmma::load_matrix_sync(oacc[i],
                                       accs + (wm * 32 + i * 16) * SLD + wn * 16,
                                       SLD, wmma::mem_row_major);
#pragma unroll
            for (int ks = 0; ks < 4; ks++) {
                wmma::fragment<wmma::matrix_b, 16, 16, 16, __nv_bfloat16, wmma::row_major> bh, bl;
                wmma::load_matrix_sync(bh, vh + (ks * 16) * AQLD + wn * 16, AQLD);
                wmma::load_matrix_sync(bl, vl + (ks * 16) * AQLD + wn * 16, AQLD);
#pragma unroll
                for (int i = 0; i < 2; i++) {
                    wmma::fragment<wmma::matrix_a, 16, 16, 16, __nv_bfloat16, wmma::row_major> ap, alp;
                    wmma::load_matrix_sync(ap,  ph + (wm * 32 + i * 16) * AQLD + ks * 16, AQLD);
                    wmma::load_matrix_sync(alp, pl + (wm * 32 + i * 16) * AQLD + ks * 16, AQLD);
                    wmma::mma_sync(oacc[i], ap,  bh, oacc[i]);
                    wmma::mma_sync(oacc[i], alp, bh, oacc[i]);
                    wmma::mma_sync(oacc[i], ap,  bl, oacc[i]);
                }
            }
#pragma unroll
            for (int i = 0; i < 2; i++)
                wmma::store_matrix_sync(accs + (wm * 32 + i * 16) * SLD + wn * 16,
                                        oacc[i], SLD, wmma::mem_row_major);
        }
    }
    __syncthreads();

    // out[b, q0+r, h*64 + c] = accs / l
#pragma unroll
    for (int p = 0; p < 4; p++) {
        int r = tr + p * 16;
        float inv = 1.0f / l_s[r];
        float4 ac = *(float4*)(accs + r * SLD + tc);
        ac.x *= inv; ac.y *= inv; ac.z *= inv; ac.w *= inv;
        size_t o = ((size_t)(b * SEQ + q0 + r)) * DMODEL + h * HDIM + tc;
        *(float4*)(out + o) = ac;
    }
}

// ============================================================================
// LayerNorm over D=1024. SPLIT=1: also emit bf16 hi/lo planes (feeds GEMM).
// ============================================================================
template <int SPLIT>
__global__ __launch_bounds__(256)
void ln_kernel(const float* __restrict__ x, const float* __restrict__ gw,
               const float* __restrict__ bw, float* __restrict__ out,
               __nv_bfloat16* __restrict__ oh, __nv_bfloat16* __restrict__ ol)
{
    __shared__ float red[16];
    __shared__ float stats[2];
    const int row = blockIdx.x;
    const int tid = threadIdx.x;
    const float* xr = x + (size_t)row * DMODEL;

    float4 xv = *(const float4*)(xr + tid * 4);
    float s  = xv.x + xv.y + xv.z + xv.w;
    float s2 = xv.x * xv.x + xv.y * xv.y + xv.z * xv.z + xv.w * xv.w;
#pragma unroll
    for (int o = 16; o > 0; o >>= 1) {
        s  += __shfl_xor_sync(0xffffffffu, s, o);
        s2 += __shfl_xor_sync(0xffffffffu, s2, o);
    }
    if ((tid & 31) == 0) { red[tid >> 5] = s; red[8 + (tid >> 5)] = s2; }
    __syncthreads();
    if (tid == 0) {
        float ts = 0.f, ts2 = 0.f;
#pragma unroll
        for (int i = 0; i < 8; i++) { ts += red[i]; ts2 += red[8 + i]; }
        float mu  = ts * (1.0f / DMODEL);
        float var = ts2 * (1.0f / DMODEL) - mu * mu;
        stats[0] = mu;
        stats[1] = rsqrtf(var + 1e-5f);
    }
    __syncthreads();
    float mu = stats[0], rstd = stats[1];
    float4 gv = *(const float4*)(gw + tid * 4);
    float4 bv = *(const float4*)(bw + tid * 4);
    float4 ov;
    ov.x = (xv.x - mu) * rstd * gv.x + bv.x;
    ov.y = (xv.y - mu) * rstd * gv.y + bv.y;
    ov.z = (xv.z - mu) * rstd * gv.z + bv.z;
    ov.w = (xv.w - mu) * rstd * gv.w + bv.w;
    *(float4*)(out + (size_t)row * DMODEL + tid * 4) = ov;
    if constexpr (SPLIT == 1) {
        split_store4(ov, oh + (size_t)row * DMODEL + tid * 4,
                         ol + (size_t)row * DMODEL + tid * 4);
    }
}

// ============================================================================
extern "C" void kernel_launch(void* const* d_in, const int* in_sizes, int n_in,
                              void* d_out, int out_size)
{
    const float* src = (const float*)d_in[0];
    const float* wq  = (const float*)d_in[1];
    const float* bq  = (const float*)d_in[2];
    const float* wk  = (const float*)d_in[3];
    const float* bk  = (const float*)d_in[4];
    const float* wv  = (const float*)d_in[5];
    const float* bv  = (const float*)d_in[6];
    const float* w1  = (const float*)d_in[7];
    const float* b1  = (const float*)d_in[8];
    const float* w2  = (const float*)d_in[9];
    const float* b2  = (const float*)d_in[10];
    const float* g1  = (const float*)d_in[11];
    const float* be1 = (const float*)d_in[12];
    const float* g2  = (const float*)d_in[13];
    const float* be2 = (const float*)d_in[14];
    float* out = (float*)d_out;

    cudaFuncSetAttribute(gemm_split<0>, cudaFuncAttributeMaxDynamicSharedMemorySize, SPLIT_SMEM);
    cudaFuncSetAttribute(gemm_split<1>, cudaFuncAttributeMaxDynamicSharedMemorySize, SPLIT_SMEM);
    cudaFuncSetAttribute(gemm_split<2>, cudaFuncAttributeMaxDynamicSharedMemorySize, SPLIT_SMEM);
    cudaFuncSetAttribute(attn_kernel, cudaFuncAttributeMaxDynamicSharedMemorySize, ATTN_SMEM);

    float *attn, *xln, *y, *bqkv;
    __nv_bfloat16 *srch, *srcl, *wqkvh, *wqkvl, *w1h, *w1l, *w2h, *w2l;
    __nv_bfloat16 *xh, *xl, *hh, *hl, *qkvh, *qkvl;
    cudaGetSymbolAddress((void**)&attn, g_attn);
    cudaGetSymbolAddress((void**)&xln,  g_xln);
    cudaGetSymbolAddress((void**)&y,    g_y);
    cudaGetSymbolAddress((void**)&bqkv, g_bqkv);
    cudaGetSymbolAddress((void**)&srch, g_srch);
    cudaGetSymbolAddress((void**)&srcl, g_srcl);
    cudaGetSymbolAddress((void**)&wqkvh, g_wqkvh);
    cudaGetSymbolAddress((void**)&wqkvl, g_wqkvl);
    cudaGetSymbolAddress((void**)&w1h, g_w1h);
    cudaGetSymbolAddress((void**)&w1l, g_w1l);
    cudaGetSymbolAddress((void**)&w2h, g_w2h);
    cudaGetSymbolAddress((void**)&w2l, g_w2l);
    cudaGetSymbolAddress((void**)&xh,  g_xh);
    cudaGetSymbolAddress((void**)&xl,  g_xl);
    cudaGetSymbolAddress((void**)&hh,  g_hh);
    cudaGetSymbolAddress((void**)&hl,  g_hl);
    cudaGetSymbolAddress((void**)&qkvh, g_qkvh);
    cudaGetSymbolAddress((void**)&qkvl, g_qkvl);

    // 0: fused split prepass
    round_all<<<(RA_TOTAL + 255) / 256, 256>>>(src, wq, wk, wv, w1, w2, bq, bk, bv,
                                               srch, srcl, wqkvh, wqkvl,
                                               w1h, w1l, w2h, w2l, bqkv);

    // 1: fused QKV GEMM (N = 3072) -> split q/k/v planes
    dim3 gQKV(3 * DMODEL / BN, MROWS / BM);        // (24, 128)
    gemm_split<0><<<gQKV, 256, SPLIT_SMEM>>>(srch, srcl, wqkvh, wqkvl, bqkv, nullptr,
                                             nullptr, qkvh, qkvl,
                                             DMODEL, 3 * DMODEL);

    // 2: attention (bf16x3)
    attn_kernel<<<BATCH * NHEAD * (SEQ / 64), 256, ATTN_SMEM>>>(qkvh, qkvl, attn);

    // 3: LN1 (fp32 + bf16 split out)
    ln_kernel<1><<<MROWS, 256>>>(attn, g1, be1, xln, xh, xl);

    // 4: FFN1 -> bf16 split h
    dim3 gF1(DFF / BN, MROWS / BM);                // (32, 128)
    gemm_split<1><<<gF1, 256, SPLIT_SMEM>>>(xh, xl, w1h, w1l, b1, nullptr,
                                            nullptr, hh, hl,
                                            DMODEL, DFF);

    // 5: FFN2 (+residual)
    dim3 gF2(DMODEL / BN, MROWS / BM);             // (8, 128)
    gemm_split<2><<<gF2, 256, SPLIT_SMEM>>>(hh, hl, w2h, w2l, b2, xln,
                                            y, nullptr, nullptr,
                                            DFF, DMODEL);

    // 6: LN2 -> out
    ln_kernel<0><<<MROWS, 256>>>(y, g2, be2, out, nullptr, nullptr);
}

// round 12
// speedup vs baseline: 1.4922x; 1.4922x over previous
#include <cuda_runtime.h>
#include <cuda_fp16.h>
#include <mma.h>
#include <cstdint>

using namespace nvcuda;

// Problem constants
#define BATCH  4
#define SEQ    4096
#define DMODEL 1024
#define NHEAD  16
#define HDIM   64
#define DFF    4096
#define WIN    512
#define MROWS  (BATCH*SEQ)          // 16384

// ---------------- scratch (device globals; no allocations allowed) ----------
static __device__ float g_attn[(size_t)MROWS * DMODEL];
static __device__ float g_xln [(size_t)MROWS * DMODEL];
static __device__ float g_y   [(size_t)MROWS * DMODEL];
// fp16 planes: activations hi/lo, weights hi only
static __device__ __align__(16) __half g_srch[(size_t)MROWS * DMODEL];
static __device__ __align__(16) __half g_srcl[(size_t)MROWS * DMODEL];
static __device__ __align__(16) __half g_wqkvh[(size_t)3 * DMODEL * DMODEL];
static __device__ __align__(16) __half g_w1h[(size_t)DFF * DMODEL];
static __device__ __align__(16) __half g_w2h[(size_t)DMODEL * DFF];
static __device__ __align__(16) __half g_xh [(size_t)MROWS * DMODEL];
static __device__ __align__(16) __half g_xl [(size_t)MROWS * DMODEL];
static __device__ __align__(16) __half g_hh [(size_t)MROWS * DFF];
static __device__ __align__(16) __half g_hl [(size_t)MROWS * DFF];
// q/k/v planes, [3][B,H,S,d]: hi for all, lo used only for q
static __device__ __align__(16) __half g_qkvh[(size_t)3 * MROWS * DMODEL];
static __device__ __align__(16) __half g_qkvl[(size_t)MROWS * DMODEL];
static __device__ float g_bqkv[3 * DMODEL];

__device__ __forceinline__ void cp16(void* dst, const void* src) {
    unsigned int d = (unsigned int)__cvta_generic_to_shared(dst);
    asm volatile("cp.async.cg.shared.global [%0], [%1], 16;\n" :: "r"(d), "l"(src));
}

// split 4 fp32 into fp16 hi/lo (8B store each)
__device__ __forceinline__ void split_store4(float4 x, __half* hp, __half* lp) {
    __half h0 = __float2half_rn(x.x);
    __half h1 = __float2half_rn(x.y);
    __half h2 = __float2half_rn(x.z);
    __half h3 = __float2half_rn(x.w);
    __half l0 = __float2half_rn(x.x - __half2float(h0));
    __half l1 = __float2half_rn(x.y - __half2float(h1));
    __half l2 = __float2half_rn(x.z - __half2float(h2));
    __half l3 = __float2half_rn(x.w - __half2float(h3));
    ((__half2*)hp)[0] = __halves2half2(h0, h1);
    ((__half2*)hp)[1] = __halves2half2(h2, h3);
    ((__half2*)lp)[0] = __halves2half2(l0, l1);
    ((__half2*)lp)[1] = __halves2half2(l2, l3);
}

__device__ __forceinline__ void hi_store4(float4 x, __half* hp) {
    ((__half2*)hp)[0] = __floats2half2_rn(x.x, x.y);
    ((__half2*)hp)[1] = __floats2half2_rn(x.z, x.w);
}

// ============================================================================
// Fused prepass: src -> fp16 hi/lo; weights -> fp16 hi only; bias pack fp32.
// Indices are float4 groups.
// ============================================================================
#define RA_TOTAL 7078656
__global__ __launch_bounds__(256)
void round_all(const float* __restrict__ src,
               const float* __restrict__ wq, const float* __restrict__ wk,
               const float* __restrict__ wv, const float* __restrict__ w1,
               const float* __restrict__ w2, const float* __restrict__ bq,
               const float* __restrict__ bk, const float* __restrict__ bv,
               __half* __restrict__ srch, __half* __restrict__ srcl,
               __half* __restrict__ wqkvh,
               __half* __restrict__ w1h, __half* __restrict__ w2h,
               float* __restrict__ bqkv)
{
    long long i = (long long)blockIdx.x * 256 + threadIdx.x;
    if (i >= RA_TOTAL) return;
    if (i >= 7077888) {                 // bias pack, fp32 copy
        long long j = i - 7077888;      // 0..767
        const float* in;
        float* op;
        if (j < 256)      { in = bq + j * 4;         op = bqkv + j * 4; }
        else if (j < 512) { in = bk + (j - 256) * 4; op = bqkv + 1024 + (j - 256) * 4; }
        else              { in = bv + (j - 512) * 4; op = bqkv + 2048 + (j - 512) * 4; }
        *(float4*)op = *(const float4*)in;
        return;
    }
    if (i < 4194304) {                  // src: split
        split_store4(*(const float4*)(src + i * 4), srch + i * 4, srcl + i * 4);
        return;
    }
    const float* in;
    __half* hp;
    if (i < 4456448)      { long long j = i - 4194304; in = wq + j * 4; hp = wqkvh + j * 4; }
    else if (i < 4718592) { long long j = i - 4456448; in = wk + j * 4; hp = wqkvh + 1048576 + j * 4; }
    else if (i < 4980736) { long long j = i - 4718592; in = wv + j * 4; hp = wqkvh + 2097152 + j * 4; }
    else if (i < 6029312) { long long j = i - 4980736; in = w1 + j * 4; hp = w1h + j * 4; }
    else                  { long long j = i - 6029312; in = w2 + j * 4; hp = w2h + j * 4; }
    hi_store4(*(const float4*)in, hp);
}

// ============================================================================
// fp16x2 TN GEMM: C = (Ah+Al) @ Wh^T  (2 MMAs per product)
// Block 128x128, BK=32, 256 thr = 8 warps as 4(m:32) x 2(n:64);
// warp tile 32x64 via m16n16k16 fp16 wmma (ldmatrix path).
//   MODE 0: +bias(packed), QKV scatter: q -> hi+lo planes, k/v -> hi only
//   MODE 1: +bias, ReLU, split-store fp16 pair (FFN1)
//   MODE 2: +bias, +extra fp32 residual, fp32 out (FFN2)
// ============================================================================
#define BM 128
#define BN 128
#define BK 32
#define LDB 40                       // halfs per row (80B)
#define PLANE (128 * LDB)            // 5120 halfs
#define STG (3 * PLANE)              // Ah|Al|Wh = 15360 halfs = 30720 B
#define SPLIT_SMEM 69632             // max(2*STG*2, epilogue 8*32*68*4)
#define QKV_PLANE ((size_t)MROWS * DMODEL)

template <int MODE>
__global__ __launch_bounds__(256, 2)
void gemm_split(const __half* __restrict__ Ah, const __half* __restrict__ Al,
                const __half* __restrict__ Wh,
                const float* __restrict__ bias, const float* __restrict__ extra,
                float* __restrict__ out0,
                __half* __restrict__ oh, __half* __restrict__ ol,
                int K, int N)
{
    extern __shared__ __half smp[];
    const int tid = threadIdx.x;
    const int wid = tid >> 5;
    const int lane = tid & 31;
    const int wm = wid & 3;      // 0..3 (32-row strips)
    const int wn = wid >> 2;     // 0..1 (64-col strips)

    wmma::fragment<wmma::accumulator, 16, 16, 16, float> acc[2][4];
#pragma unroll
    for (int i = 0; i < 2; i++)
#pragma unroll
        for (int j = 0; j < 4; j++)
            wmma::fill_fragment(acc[i][j], 0.0f);

    const __half* Ahg = Ah + (size_t)blockIdx.y * BM * K;
    const __half* Alg = Al + (size_t)blockIdx.y * BM * K;
    const __half* Whg = Wh + (size_t)blockIdx.x * BN * K;

    auto load_stage = [&](int s, int kt) {
        __half* st = smp + s * STG;
#pragma unroll
        for (int p = 0; p < 2; p++) {
            int c = tid + p * 256;            // 0..511
            int r = c >> 2, col = (c & 3) * 8;
            size_t go = (size_t)r * K + kt + col;
            unsigned so = r * LDB + col;
            cp16(st + so,             Ahg + go);
            cp16(st + PLANE + so,     Alg + go);
            cp16(st + 2 * PLANE + so, Whg + go);
        }
        asm volatile("cp.async.commit_group;\n");
    };

    const int T = K / BK;
    load_stage(0, 0);

    for (int t = 0; t < T; t++) {
        const int cur = t & 1;
        if (t + 1 < T) {
            load_stage(cur ^ 1, (t + 1) * BK);
            asm volatile("cp.async.wait_group 1;\n");
        } else {
            asm volatile("cp.async.wait_group 0;\n");
        }
        __syncthreads();

        const __half* Ahs = smp + cur * STG;
        const __half* Als = Ahs + PLANE;
        const __half* Bhs = Ahs + 2 * PLANE;

#pragma unroll
        for (int kk = 0; kk < BK; kk += 16) {
            wmma::fragment<wmma::matrix_a, 16, 16, 16, __half, wmma::row_major> ah[2], al[2];
#pragma unroll
            for (int i = 0; i < 2; i++) {
                wmma::load_matrix_sync(ah[i], Ahs + (wm * 32 + i * 16) * LDB + kk, LDB);
                wmma::load_matrix_sync(al[i], Als + (wm * 32 + i * 16) * LDB + kk, LDB);
            }
#pragma unroll
            for (int j = 0; j < 4; j++) {
                wmma::fragment<wmma::matrix_b, 16, 16, 16, __half, wmma::col_major> bh;
                wmma::load_matrix_sync(bh, Bhs + (wn * 64 + j * 16) * LDB + kk, LDB);
#pragma unroll
                for (int i = 0; i < 2; i++) {
                    wmma::mma_sync(acc[i][j], ah[i], bh, acc[i][j]);
                    wmma::mma_sync(acc[i][j], al[i], bh, acc[i][j]);
                }
            }
        }
        __syncthreads();
    }

    // Per-warp epilogue staging: 32x64 fp32 strip, stride 68.
    float* Cw = (float*)smp + wid * (32 * 68);
#pragma unroll
    for (int i = 0; i < 2; i++)
#pragma unroll
        for (int j = 0; j < 4; j++)
            wmma::store_matrix_sync(Cw + (i * 16) * 68 + j * 16, acc[i][j], 68,
                                    wmma::mem_row_major);
    __syncwarp();

    const int m = blockIdx.y * BM + wm * 32 + lane;
    const int n0 = blockIdx.x * BN + wn * 64;
    const float* crow = Cw + lane * 68;

#pragma unroll
    for (int c4 = 0; c4 < 16; c4++) {
        int n = n0 + c4 * 4;
        float4 c = *(float4*)(crow + c4 * 4);
        float4 bb = *(const float4*)(bias + n);
        c.x += bb.x; c.y += bb.y; c.z += bb.z; c.w += bb.w;
        if constexpr (MODE == 1) {
            c.x = fmaxf(c.x, 0.f); c.y = fmaxf(c.y, 0.f);
            c.z = fmaxf(c.z, 0.f); c.w = fmaxf(c.w, 0.f);
            split_store4(c, oh + (size_t)m * N + n, ol + (size_t)m * N + n);
        } else if constexpr (MODE == 2) {
            float4 e = *(const float4*)(extra + (size_t)m * N + n);
            c.x += e.x; c.y += e.y; c.z += e.z; c.w += e.w;
            *(float4*)(out0 + (size_t)m * N + n) = c;
        } else {
            int mat = n >> 10;
            int nl  = n & 1023;
            int h   = nl >> 6;
            int dd  = nl & (HDIM - 1);
            int bi  = m >> 12;
            int s   = m & (SEQ - 1);
            size_t o = (((size_t)bi * NHEAD + h) * SEQ + s) * HDIM + dd;
            if (mat == 0) split_store4(c, oh + o, ol + o);
            else          hi_store4(c, oh + mat * QKV_PLANE + o);
        }
    }
}

// ============================================================================
// Windowed causal flash attention, fp16x2:
// S = (qh+ql) @ kh^T ; O += (Ph+Pl) @ vh — k/v lo never needed.
// Planes: qh, ql, kh, vh, ph, pl. Block = (b,h,64-row q chunk), 256 thr,
// 8 warps as 2(m:32) x 4(n:16).
// ============================================================================
#define AQLD 72                     // halfs per row (144B)
#define APLANE (64 * AQLD)          // 4608 halfs
#define SLD 68                      // fp32 stride for S and acc
#define ATTN_SMEM (6 * APLANE * 2 + 2 * 64 * SLD * 4 + 2 * 64 * 4)  // 90624 B

__global__ __launch_bounds__(256, 2)
void attn_kernel(const __half* __restrict__ qkvh,
                 const __half* __restrict__ qlo,
                 float* __restrict__ out)
{
    const int idx = blockIdx.x;
    const int qc = idx & 7;
    const int w  = (idx >> 3) & 7;
    const int h  = (idx >> 6) & 15;
    const int b  = idx >> 10;

    extern __shared__ char smc[];
    __half* qh = (__half*)smc;
    __half* ql = qh + APLANE;
    __half* kh = qh + 2 * APLANE;
    __half* vh = qh + 3 * APLANE;
    __half* ph = qh + 4 * APLANE;
    __half* pl = qh + 5 * APLANE;
    float* s_s  = (float*)(smc + 6 * APLANE * 2);
    float* accs = s_s + 64 * SLD;
    float* m_s  = accs + 64 * SLD;
    float* l_s  = m_s + 64;

    const int tid = threadIdx.x;
    const int wid = tid >> 5;
    const int wm  = wid & 1;    // 0..1 (32-row strips)
    const int wn  = wid >> 1;   // 0..3 (16-col strips)
    const size_t NM = QKV_PLANE;
    const size_t headbase = ((size_t)(b * NHEAD + h)) * SEQ * HDIM;
    const int q0 = w * WIN + qc * 64;

    const int tr = tid >> 4;           // 0..15
    const int tc = (tid & 15) << 2;    // 0..60 step 4

    // load q hi/lo planes (each 64 rows x 64 halfs = 512 8-half chunks)
    {
        const __half* qgh = qkvh + headbase + (size_t)q0 * HDIM;
        const __half* qgl = qlo  + headbase + (size_t)q0 * HDIM;
#pragma unroll
        for (int p = 0; p < 4; p++) {
            int c = tid + p * 256;          // 0..1023
            int plane = c >> 9;
            int cc = c & 511;
            int r = cc >> 3, col = (cc & 7) * 8;
            const __half* s = (plane ? qgl : qgh) + (size_t)r * HDIM + col;
            __half* d = (plane ? ql : qh) + r * AQLD + col;
            *(uint4*)d = *(const uint4*)s;
        }
    }
#pragma unroll
    for (int p = 0; p < 4; p++) {
        int r = tr + p * 16;
        *(float4*)(accs + r * SLD + tc) = make_float4(0.f, 0.f, 0.f, 0.f);
    }
    if (tid < 64) { m_s[tid] = -1e30f; l_s[tid] = 0.f; }

    const int kstart = (w == 0) ? 0 : (w - 1) * WIN;
    const int kend   = q0 + 64;

    const __half* kgh = qkvh + NM + headbase;
    const __half* vgh = qkvh + 2 * NM + headbase;

    for (int kc = kstart; kc < kend; kc += 64) {
        __syncthreads();   // prev PV complete before overwriting k/v planes

        // load kh/vh planes (2 x 512 chunks)
#pragma unroll
        for (int p = 0; p < 4; p++) {
            int c = tid + p * 256;          // 0..1023
            int plane = c >> 9;             // 0:kh 1:vh
            int cc = c & 511;
            int r = cc >> 3, col = (cc & 7) * 8;
            const __half* s = (plane ? vgh : kgh) + (size_t)(kc + r) * HDIM + col;
            __half* d = (plane ? vh : kh) + r * AQLD + col;
            *(uint4*)d = *(const uint4*)s;
        }
        __syncthreads();   // k/v ready

        // S = (qh+ql) @ kh^T
        {
            wmma::fragment<wmma::accumulator, 16, 16, 16, float> sacc[2];
#pragma unroll
            for (int i = 0; i < 2; i++) wmma::fill_fragment(sacc[i], 0.0f);
#pragma unroll
            for (int ks = 0; ks < 4; ks++) {
                wmma::fragment<wmma::matrix_b, 16, 16, 16, __half, wmma::col_major> bh;
                wmma::load_matrix_sync(bh, kh + (wn * 16) * AQLD + ks * 16, AQLD);
#pragma unroll
                for (int i = 0; i < 2; i++) {
                    wmma::fragment<wmma::matrix_a, 16, 16, 16, __half, wmma::row_major> ah, al;
                    wmma::load_matrix_sync(ah, qh + (wm * 32 + i * 16) * AQLD + ks * 16, AQLD);
                    wmma::load_matrix_sync(al, ql + (wm * 32 + i * 16) * AQLD + ks * 16, AQLD);
                    wmma::mma_sync(sacc[i], ah, bh, sacc[i]);
                    wmma::mma_sync(sacc[i], al, bh, sacc[i]);
                }
            }
#pragma unroll
            for (int i = 0; i < 2; i++)
                wmma::store_matrix_sync(s_s + (wm * 32 + i * 16) * SLD + wn * 16,
                                        sacc[i], SLD, wmma::mem_row_major);
        }
        __syncthreads();   // scores ready

        // online softmax (1/8 scale here); P split-stored to ph/pl
        {
            const bool diag = (kc == q0);
            const int r  = tid >> 2;           // 0..63
            const int c0 = (tid & 3) << 4;     // 0,16,32,48
            float* srow = s_s + r * SLD + c0;
            float sv[16];
            float mloc = -1e30f;
#pragma unroll
            for (int t = 0; t < 16; t++) {
                float x = srow[t] * 0.125f;
                if (diag && (c0 + t > r)) x = -1e30f;
                sv[t] = x;
                mloc = fmaxf(mloc, x);
            }
            mloc = fmaxf(mloc, __shfl_xor_sync(0xffffffffu, mloc, 1));
            mloc = fmaxf(mloc, __shfl_xor_sync(0xffffffffu, mloc, 2));
            float mold = m_s[r];
            float mnew = fmaxf(mold, mloc);
            float ssum = 0.f;
#pragma unroll
            for (int t = 0; t < 16; t += 2) {
                float p0 = __expf(sv[t]     - mnew);
                float p1 = __expf(sv[t + 1] - mnew);
                ssum += p0 + p1;
                __half h0 = __float2half_rn(p0);
                __half h1 = __float2half_rn(p1);
                __half l0 = __float2half_rn(p0 - __half2float(h0));
                __half l1 = __float2half_rn(p1 - __half2float(h1));
                *(__half2*)(ph + r * AQLD + c0 + t) = __halves2half2(h0, h1);
                *(__half2*)(pl + r * AQLD + c0 + t) = __halves2half2(l0, l1);
            }
            ssum += __shfl_xor_sync(0xffffffffu, ssum, 1);
            ssum += __shfl_xor_sync(0xffffffffu, ssum, 2);
            float alpha = __expf(mold - mnew);   // 0 on first chunk
            if ((tid & 3) == 0) {
                m_s[r] = mnew;
                l_s[r] = l_s[r] * alpha + ssum;
            }
            // rescale accumulator rows in-place
            float* arow = accs + r * SLD + c0;
#pragma unroll
            for (int t = 0; t < 4; t++) {
                float4 a4 = *(float4*)(arow + t * 4);
                a4.x *= alpha; a4.y *= alpha; a4.z *= alpha; a4.w *= alpha;
                *(float4*)(arow + t * 4) = a4;
            }
        }
        __syncthreads();   // P planes + scaled accs ready

        // accs += (Ph+Pl) @ vh
        {
            wmma::fragment<wmma::accumulator, 16, 16, 16, float> oacc[2];
#pragma unroll
            for (int i = 0; i < 2; i++)
                wmma::load_matrix_sync(oacc[i],
                                       accs + (wm * 32 + i * 16) * SLD + wn * 16,
                                       SLD, wmma::mem_row_major);
#pragma unroll
            for (int ks = 0; ks < 4; ks++) {
                wmma::fragment<wmma::matrix_b, 16, 16, 16, __half, wmma::row_major> bh;
                wmma::load_matrix_sync(bh, vh + (ks * 16) * AQLD + wn * 16, AQLD);
#pragma unroll
                for (int i = 0; i < 2; i++) {
                    wmma::fragment<wmma::matrix_a, 16, 16, 16, __half, wmma::row_major> ap, alp;
                    wmma::load_matrix_sync(ap,  ph + (wm * 32 + i * 16) * AQLD + ks * 16, AQLD);
                    wmma::load_matrix_sync(alp, pl + (wm * 32 + i * 16) * AQLD + ks * 16, AQLD);
                    wmma::mma_sync(oacc[i], ap,  bh, oacc[i]);
                    wmma::mma_sync(oacc[i], alp, bh, oacc[i]);
                }
            }
#pragma unroll
            for (int i = 0; i < 2; i++)
                wmma::store_matrix_sync(accs + (wm * 32 + i * 16) * SLD + wn * 16,
                                        oacc[i], SLD, wmma::mem_row_major);
        }
    }
    __syncthreads();

    // out[b, q0+r, h*64 + c] = accs / l
#pragma unroll
    for (int p = 0; p < 4; p++) {
        int r = tr + p * 16;
        float inv = 1.0f / l_s[r];
        float4 ac = *(float4*)(accs + r * SLD + tc);
        ac.x *= inv; ac.y *= inv; ac.z *= inv; ac.w *= inv;
        size_t o = ((size_t)(b * SEQ + q0 + r)) * DMODEL + h * HDIM + tc;
        *(float4*)(out + o) = ac;
    }
}

// ============================================================================
// LayerNorm over D=1024. SPLIT=1: also emit fp16 hi/lo planes (feeds GEMM).
// ============================================================================
template <int SPLIT>
__global__ __launch_bounds__(256)
void ln_kernel(const float* __restrict__ x, const float* __restrict__ gw,
               const float* __restrict__ bw, float* __restrict__ out,
               __half* __restrict__ oh, __half* __restrict__ ol)
{
    __shared__ float red[16];
    __shared__ float stats[2];
    const int row = blockIdx.x;
    const int tid = threadIdx.x;
    const float* xr = x + (size_t)row * DMODEL;

    float4 xv = *(const float4*)(xr + tid * 4);
    float s  = xv.x + xv.y + xv.z + xv.w;
    float s2 = xv.x * xv.x + xv.y * xv.y + xv.z * xv.z + xv.w * xv.w;
#pragma unroll
    for (int o = 16; o > 0; o >>= 1) {
        s  += __shfl_xor_sync(0xffffffffu, s, o);
        s2 += __shfl_xor_sync(0xffffffffu, s2, o);
    }
    if ((tid & 31) == 0) { red[tid >> 5] = s; red[8 + (tid >> 5)] = s2; }
    __syncthreads();
    if (tid == 0) {
        float ts = 0.f, ts2 = 0.f;
#pragma unroll
        for (int i = 0; i < 8; i++) { ts += red[i]; ts2 += red[8 + i]; }
        float mu  = ts * (1.0f / DMODEL);
        float var = ts2 * (1.0f / DMODEL) - mu * mu;
        stats[0] = mu;
        stats[1] = rsqrtf(var + 1e-5f);
    }
    __syncthreads();
    float mu = stats[0], rstd = stats[1];
    float4 gv = *(const float4*)(gw + tid * 4);
    float4 bv = *(const float4*)(bw + tid * 4);
    float4 ov;
    ov.x = (xv.x - mu) * rstd * gv.x + bv.x;
    ov.y = (xv.y - mu) * rstd * gv.y + bv.y;
    ov.z = (xv.z - mu) * rstd * gv.z + bv.z;
    ov.w = (xv.w - mu) * rstd * gv.w + bv.w;
    *(float4*)(out + (size_t)row * DMODEL + tid * 4) = ov;
    if constexpr (SPLIT == 1) {
        split_store4(ov, oh + (size_t)row * DMODEL + tid * 4,
                         ol + (size_t)row * DMODEL + tid * 4);
    }
}

// ============================================================================
extern "C" void kernel_launch(void* const* d_in, const int* in_sizes, int n_in,
                              void* d_out, int out_size)
{
    const float* src = (const float*)d_in[0];
    const float* wq  = (const float*)d_in[1];
    const float* bq  = (const float*)d_in[2];
    const float* wk  = (const float*)d_in[3];
    const float* bk  = (const float*)d_in[4];
    const float* wv  = (const float*)d_in[5];
    const float* bv  = (const float*)d_in[6];
    const float* w1  = (const float*)d_in[7];
    const float* b1  = (const float*)d_in[8];
    const float* w2  = (const float*)d_in[9];
    const float* b2  = (const float*)d_in[10];
    const float* g1  = (const float*)d_in[11];
    const float* be1 = (const float*)d_in[12];
    const float* g2  = (const float*)d_in[13];
    const float* be2 = (const float*)d_in[14];
    float* out = (float*)d_out;

    cudaFuncSetAttribute(gemm_split<0>, cudaFuncAttributeMaxDynamicSharedMemorySize, SPLIT_SMEM);
    cudaFuncSetAttribute(gemm_split<1>, cudaFuncAttributeMaxDynamicSharedMemorySize, SPLIT_SMEM);
    cudaFuncSetAttribute(gemm_split<2>, cudaFuncAttributeMaxDynamicSharedMemorySize, SPLIT_SMEM);
    cudaFuncSetAttribute(attn_kernel, cudaFuncAttributeMaxDynamicSharedMemorySize, ATTN_SMEM);

    float *attn, *xln, *y, *bqkv;
    __half *srch, *srcl, *wqkvh, *w1h, *w2h, *xh, *xl, *hh, *hl, *qkvh, *qkvl;
    cudaGetSymbolAddress((void**)&attn, g_attn);
    cudaGetSymbolAddress((void**)&xln,  g_xln);
    cudaGetSymbolAddress((void**)&y,    g_y);
    cudaGetSymbolAddress((void**)&bqkv, g_bqkv);
    cudaGetSymbolAddress((void**)&srch, g_srch);
    cudaGetSymbolAddress((void**)&srcl, g_srcl);
    cudaGetSymbolAddress((void**)&wqkvh, g_wqkvh);
    cudaGetSymbolAddress((void**)&w1h, g_w1h);
    cudaGetSymbolAddress((void**)&w2h, g_w2h);
    cudaGetSymbolAddress((void**)&xh,  g_xh);
    cudaGetSymbolAddress((void**)&xl,  g_xl);
    cudaGetSymbolAddress((void**)&hh,  g_hh);
    cudaGetSymbolAddress((void**)&hl,  g_hl);
    cudaGetSymbolAddress((void**)&qkvh, g_qkvh);
    cudaGetSymbolAddress((void**)&qkvl, g_qkvl);

    // 0: fused prepass (src split, weights hi, bias pack)
    round_all<<<(RA_TOTAL + 255) / 256, 256>>>(src, wq, wk, wv, w1, w2, bq, bk, bv,
                                               srch, srcl, wqkvh, w1h, w2h, bqkv);

    // 1: fused QKV GEMM (N = 3072) -> q hi/lo, k/v hi
    dim3 gQKV(3 * DMODEL / BN, MROWS / BM);        // (24, 128)
    gemm_split<0><<<gQKV, 256, SPLIT_SMEM>>>(srch, srcl, wqkvh, bqkv, nullptr,
                                             nullptr, qkvh, qkvl,
                                             DMODEL, 3 * DMODEL);

    // 2: attention (fp16x2)
    attn_kernel<<<BATCH * NHEAD * (SEQ / 64), 256, ATTN_SMEM>>>(qkvh, qkvl, attn);

    // 3: LN1 (fp32 + fp16 split out)
    ln_kernel<1><<<MROWS, 256>>>(attn, g1, be1, xln, xh, xl);

    // 4: FFN1 -> fp16 split h
    dim3 gF1(DFF / BN, MROWS / BM);                // (32, 128)
    gemm_split<1><<<gF1, 256, SPLIT_SMEM>>>(xh, xl, w1h, b1, nullptr,
                                            nullptr, hh, hl,
                                            DMODEL, DFF);

    // 5: FFN2 (+residual)
    dim3 gF2(DMODEL / BN, MROWS / BM);             // (8, 128)
    gemm_split<2><<<gF2, 256, SPLIT_SMEM>>>(hh, hl, w2h, b2, xln,
                                            y, nullptr, nullptr,
                                            DFF, DMODEL);

    // 6: LN2 -> out
    ln_kernel<0><<<MROWS, 256>>>(y, g2, be2, out, nullptr, nullptr);
}

// round 13
// speedup vs baseline: 2.3805x; 1.5953x over previous
#include <cuda_runtime.h>
#include <cuda_fp16.h>
#include <mma.h>
#include <cstdint>

using namespace nvcuda;

// Problem constants
#define BATCH  4
#define SEQ    4096
#define DMODEL 1024
#define NHEAD  16
#define HDIM   64
#define DFF    4096
#define WIN    512
#define MROWS  (BATCH*SEQ)          // 16384

// ---------------- scratch (device globals; no allocations allowed) ----------
static __device__ float g_attn[(size_t)MROWS * DMODEL];
static __device__ float g_xln [(size_t)MROWS * DMODEL];
static __device__ float g_y   [(size_t)MROWS * DMODEL];
// fp16 planes (hi only — plain fp16 path)
static __device__ __align__(16) __half g_srch[(size_t)MROWS * DMODEL];
static __device__ __align__(16) __half g_wqkvh[(size_t)3 * DMODEL * DMODEL];
static __device__ __align__(16) __half g_w1h[(size_t)DFF * DMODEL];
static __device__ __align__(16) __half g_w2h[(size_t)DMODEL * DFF];
static __device__ __align__(16) __half g_xh [(size_t)MROWS * DMODEL];
static __device__ __align__(16) __half g_hh [(size_t)MROWS * DFF];
// q/k/v planes, [3][B,H,S,d]
static __device__ __align__(16) __half g_qkvh[(size_t)3 * MROWS * DMODEL];
static __device__ float g_bqkv[3 * DMODEL];

__device__ __forceinline__ void cp16(void* dst, const void* src) {
    unsigned int d = (unsigned int)__cvta_generic_to_shared(dst);
    asm volatile("cp.async.cg.shared.global [%0], [%1], 16;\n" :: "r"(d), "l"(src));
}

__device__ __forceinline__ void hi_store4(float4 x, __half* hp) {
    ((__half2*)hp)[0] = __floats2half2_rn(x.x, x.y);
    ((__half2*)hp)[1] = __floats2half2_rn(x.z, x.w);
}

// ============================================================================
// Fused prepass: src + weights -> fp16; bias pack fp32. float4-group indices.
// ============================================================================
#define RA_TOTAL 7078656
__global__ __launch_bounds__(256)
void round_all(const float* __restrict__ src,
               const float* __restrict__ wq, const float* __restrict__ wk,
               const float* __restrict__ wv, const float* __restrict__ w1,
               const float* __restrict__ w2, const float* __restrict__ bq,
               const float* __restrict__ bk, const float* __restrict__ bv,
               __half* __restrict__ srch, __half* __restrict__ wqkvh,
               __half* __restrict__ w1h, __half* __restrict__ w2h,
               float* __restrict__ bqkv)
{
    long long i = (long long)blockIdx.x * 256 + threadIdx.x;
    if (i >= RA_TOTAL) return;
    if (i >= 7077888) {                 // bias pack, fp32 copy
        long long j = i - 7077888;      // 0..767
        const float* in;
        float* op;
        if (j < 256)      { in = bq + j * 4;         op = bqkv + j * 4; }
        else if (j < 512) { in = bk + (j - 256) * 4; op = bqkv + 1024 + (j - 256) * 4; }
        else              { in = bv + (j - 512) * 4; op = bqkv + 2048 + (j - 512) * 4; }
        *(float4*)op = *(const float4*)in;
        return;
    }
    const float* in;
    __half* hp;
    if (i < 4194304)      { in = src + i * 4; hp = srch + i * 4; }
    else if (i < 4456448) { long long j = i - 4194304; in = wq + j * 4; hp = wqkvh + j * 4; }
    else if (i < 4718592) { long long j = i - 4456448; in = wk + j * 4; hp = wqkvh + 1048576 + j * 4; }
    else if (i < 4980736) { long long j = i - 4718592; in = wv + j * 4; hp = wqkvh + 2097152 + j * 4; }
    else if (i < 6029312) { long long j = i - 4980736; in = w1 + j * 4; hp = w1h + j * 4; }
    else                  { long long j = i - 6029312; in = w2 + j * 4; hp = w2h + j * 4; }
    hi_store4(*(const float4*)in, hp);
}

// ============================================================================
// Plain-fp16 TN GEMM: C = A @ W^T (fp32 accumulate)
// Block 128x128, BK=32, 256 thr = 8 warps as 4(m:32) x 2(n:64);
// warp tile 32x64 via m16n16k16 fp16 wmma (ldmatrix path).
//   MODE 0: +bias(packed), QKV scatter -> fp16 planes [3][B,H,S,d]
//   MODE 1: +bias, ReLU, fp16 out (FFN1)
//   MODE 2: +bias, +extra fp32 residual, fp32 out (FFN2)
// ============================================================================
#define BM 128
#define BN 128
#define BK 32
#define LDB 40                       // halfs per row (80B)
#define PLANE (128 * LDB)            // 5120 halfs
#define STG (2 * PLANE)              // A|W = 10240 halfs = 20480 B
#define SPLIT_SMEM 69632             // epilogue staging dominates (8*32*68*4)
#define QKV_PLANE ((size_t)MROWS * DMODEL)

template <int MODE>
__global__ __launch_bounds__(256, 2)
void gemm_h(const __half* __restrict__ Ah, const __half* __restrict__ Wh,
            const float* __restrict__ bias, const float* __restrict__ extra,
            float* __restrict__ out0, __half* __restrict__ oh,
            int K, int N)
{
    extern __shared__ __half smp[];
    const int tid = threadIdx.x;
    const int wid = tid >> 5;
    const int lane = tid & 31;
    const int wm = wid & 3;      // 0..3 (32-row strips)
    const int wn = wid >> 2;     // 0..1 (64-col strips)

    wmma::fragment<wmma::accumulator, 16, 16, 16, float> acc[2][4];
#pragma unroll
    for (int i = 0; i < 2; i++)
#pragma unroll
        for (int j = 0; j < 4; j++)
            wmma::fill_fragment(acc[i][j], 0.0f);

    const __half* Ahg = Ah + (size_t)blockIdx.y * BM * K;
    const __half* Whg = Wh + (size_t)blockIdx.x * BN * K;

    auto load_stage = [&](int s, int kt) {
        __half* st = smp + s * STG;
#pragma unroll
        for (int p = 0; p < 2; p++) {
            int c = tid + p * 256;            // 0..511
            int r = c >> 2, col = (c & 3) * 8;
            size_t go = (size_t)r * K + kt + col;
            unsigned so = r * LDB + col;
            cp16(st + so,         Ahg + go);
            cp16(st + PLANE + so, Whg + go);
        }
        asm volatile("cp.async.commit_group;\n");
    };

    const int T = K / BK;
    load_stage(0, 0);

    for (int t = 0; t < T; t++) {
        const int cur = t & 1;
        if (t + 1 < T) {
            load_stage(cur ^ 1, (t + 1) * BK);
            asm volatile("cp.async.wait_group 1;\n");
        } else {
            asm volatile("cp.async.wait_group 0;\n");
        }
        __syncthreads();

        const __half* Ahs = smp + cur * STG;
        const __half* Bhs = Ahs + PLANE;

#pragma unroll
        for (int kk = 0; kk < BK; kk += 16) {
            wmma::fragment<wmma::matrix_a, 16, 16, 16, __half, wmma::row_major> ah[2];
#pragma unroll
            for (int i = 0; i < 2; i++)
                wmma::load_matrix_sync(ah[i], Ahs + (wm * 32 + i * 16) * LDB + kk, LDB);
#pragma unroll
            for (int j = 0; j < 4; j++) {
                wmma::fragment<wmma::matrix_b, 16, 16, 16, __half, wmma::col_major> bh;
                wmma::load_matrix_sync(bh, Bhs + (wn * 64 + j * 16) * LDB + kk, LDB);
#pragma unroll
                for (int i = 0; i < 2; i++)
                    wmma::mma_sync(acc[i][j], ah[i], bh, acc[i][j]);
            }
        }
        __syncthreads();
    }

    // Per-warp epilogue staging: 32x64 fp32 strip, stride 68.
    float* Cw = (float*)smp + wid * (32 * 68);
#pragma unroll
    for (int i = 0; i < 2; i++)
#pragma unroll
        for (int j = 0; j < 4; j++)
            wmma::store_matrix_sync(Cw + (i * 16) * 68 + j * 16, acc[i][j], 68,
                                    wmma::mem_row_major);
    __syncwarp();

    const int m = blockIdx.y * BM + wm * 32 + lane;
    const int n0 = blockIdx.x * BN + wn * 64;
    const float* crow = Cw + lane * 68;

#pragma unroll
    for (int c4 = 0; c4 < 16; c4++) {
        int n = n0 + c4 * 4;
        float4 c = *(float4*)(crow + c4 * 4);
        float4 bb = *(const float4*)(bias + n);
        c.x += bb.x; c.y += bb.y; c.z += bb.z; c.w += bb.w;
        if constexpr (MODE == 1) {
            c.x = fmaxf(c.x, 0.f); c.y = fmaxf(c.y, 0.f);
            c.z = fmaxf(c.z, 0.f); c.w = fmaxf(c.w, 0.f);
            hi_store4(c, oh + (size_t)m * N + n);
        } else if constexpr (MODE == 2) {
            float4 e = *(const float4*)(extra + (size_t)m * N + n);
            c.x += e.x; c.y += e.y; c.z += e.z; c.w += e.w;
            *(float4*)(out0 + (size_t)m * N + n) = c;
        } else {
            int mat = n >> 10;
            int nl  = n & 1023;
            int h   = nl >> 6;
            int dd  = nl & (HDIM - 1);
            int bi  = m >> 12;
            int s   = m & (SEQ - 1);
            size_t o = (((size_t)bi * NHEAD + h) * SEQ + s) * HDIM + dd;
            hi_store4(c, oh + mat * QKV_PLANE + o);
        }
    }
}

// ============================================================================
// Windowed causal flash attention, plain fp16:
// S = q @ k^T ; O += P @ v. Planes: qh, kh, vh, ph.
// Block = (b,h,64-row q chunk), 256 thr, 8 warps as 2(m:32) x 4(n:16).
// ============================================================================
#define AQLD 72                     // halfs per row (144B)
#define APLANE (64 * AQLD)          // 4608 halfs
#define SLD 68                      // fp32 stride for S and acc
#define ATTN_SMEM (4 * APLANE * 2 + 2 * 64 * SLD * 4 + 2 * 64 * 4)  // 72192 B

__global__ __launch_bounds__(256, 2)
void attn_kernel(const __half* __restrict__ qkvh, float* __restrict__ out)
{
    const int idx = blockIdx.x;
    const int qc = idx & 7;
    const int w  = (idx >> 3) & 7;
    const int h  = (idx >> 6) & 15;
    const int b  = idx >> 10;

    extern __shared__ char smc[];
    __half* qh = (__half*)smc;
    __half* kh = qh + APLANE;
    __half* vh = qh + 2 * APLANE;
    __half* ph = qh + 3 * APLANE;
    float* s_s  = (float*)(smc + 4 * APLANE * 2);
    float* accs = s_s + 64 * SLD;
    float* m_s  = accs + 64 * SLD;
    float* l_s  = m_s + 64;

    const int tid = threadIdx.x;
    const int wid = tid >> 5;
    const int wm  = wid & 1;    // 0..1 (32-row strips)
    const int wn  = wid >> 1;   // 0..3 (16-col strips)
    const size_t NM = QKV_PLANE;
    const size_t headbase = ((size_t)(b * NHEAD + h)) * SEQ * HDIM;
    const int q0 = w * WIN + qc * 64;

    const int tr = tid >> 4;           // 0..15
    const int tc = (tid & 15) << 2;    // 0..60 step 4

    // load q plane (64 rows x 64 halfs = 512 8-half chunks)
    {
        const __half* qg = qkvh + headbase + (size_t)q0 * HDIM;
#pragma unroll
        for (int p = 0; p < 2; p++) {
            int c = tid + p * 256;          // 0..511
            int r = c >> 3, col = (c & 7) * 8;
            *(uint4*)(qh + r * AQLD + col) = *(const uint4*)(qg + (size_t)r * HDIM + col);
        }
    }
#pragma unroll
    for (int p = 0; p < 4; p++) {
        int r = tr + p * 16;
        *(float4*)(accs + r * SLD + tc) = make_float4(0.f, 0.f, 0.f, 0.f);
    }
    if (tid < 64) { m_s[tid] = -1e30f; l_s[tid] = 0.f; }

    const int kstart = (w == 0) ? 0 : (w - 1) * WIN;
    const int kend   = q0 + 64;

    const __half* kg = qkvh + NM + headbase;
    const __half* vg = qkvh + 2 * NM + headbase;

    for (int kc = kstart; kc < kend; kc += 64) {
        __syncthreads();   // prev PV complete before overwriting k/v planes

        // load kh/vh planes (2 x 512 chunks)
#pragma unroll
        for (int p = 0; p < 4; p++) {
            int c = tid + p * 256;          // 0..1023
            int plane = c >> 9;             // 0:kh 1:vh
            int cc = c & 511;
            int r = cc >> 3, col = (cc & 7) * 8;
            const __half* s = (plane ? vg : kg) + (size_t)(kc + r) * HDIM + col;
            __half* d = (plane ? vh : kh) + r * AQLD + col;
            *(uint4*)d = *(const uint4*)s;
        }
        __syncthreads();   // k/v ready

        // S = q @ k^T
        {
            wmma::fragment<wmma::accumulator, 16, 16, 16, float> sacc[2];
#pragma unroll
            for (int i = 0; i < 2; i++) wmma::fill_fragment(sacc[i], 0.0f);
#pragma unroll
            for (int ks = 0; ks < 4; ks++) {
                wmma::fragment<wmma::matrix_b, 16, 16, 16, __half, wmma::col_major> bh;
                wmma::load_matrix_sync(bh, kh + (wn * 16) * AQLD + ks * 16, AQLD);
#pragma unroll
                for (int i = 0; i < 2; i++) {
                    wmma::fragment<wmma::matrix_a, 16, 16, 16, __half, wmma::row_major> ah;
                    wmma::load_matrix_sync(ah, qh + (wm * 32 + i * 16) * AQLD + ks * 16, AQLD);
                    wmma::mma_sync(sacc[i], ah, bh, sacc[i]);
                }
            }
#pragma unroll
            for (int i = 0; i < 2; i++)
                wmma::store_matrix_sync(s_s + (wm * 32 + i * 16) * SLD + wn * 16,
                                        sacc[i], SLD, wmma::mem_row_major);
        }
        __syncthreads();   // scores ready

        // online softmax (1/8 scale here); P stored fp16
        {
            const bool diag = (kc == q0);
            const int r  = tid >> 2;           // 0..63
            const int c0 = (tid & 3) << 4;     // 0,16,32,48
            float* srow = s_s + r * SLD + c0;
            float sv[16];
            float mloc = -1e30f;
#pragma unroll
            for (int t = 0; t < 16; t++) {
                float x = srow[t] * 0.125f;
                if (diag && (c0 + t > r)) x = -1e30f;
                sv[t] = x;
                mloc = fmaxf(mloc, x);
            }
            mloc = fmaxf(mloc, __shfl_xor_sync(0xffffffffu, mloc, 1));
            mloc = fmaxf(mloc, __shfl_xor_sync(0xffffffffu, mloc, 2));
            float mold = m_s[r];
            float mnew = fmaxf(mold, mloc);
            float ssum = 0.f;
#pragma unroll
            for (int t = 0; t < 16; t += 2) {
                float p0 = __expf(sv[t]     - mnew);
                float p1 = __expf(sv[t + 1] - mnew);
                ssum += p0 + p1;
                *(__half2*)(ph + r * AQLD + c0 + t) = __floats2half2_rn(p0, p1);
            }
            ssum += __shfl_xor_sync(0xffffffffu, ssum, 1);
            ssum += __shfl_xor_sync(0xffffffffu, ssum, 2);
            float alpha = __expf(mold - mnew);   // 0 on first chunk
            if ((tid & 3) == 0) {
                m_s[r] = mnew;
                l_s[r] = l_s[r] * alpha + ssum;
            }
            // rescale accumulator rows in-place
            float* arow = accs + r * SLD + c0;
#pragma unroll
            for (int t = 0; t < 4; t++) {
                float4 a4 = *(float4*)(arow + t * 4);
                a4.x *= alpha; a4.y *= alpha; a4.z *= alpha; a4.w *= alpha;
                *(float4*)(arow + t * 4) = a4;
            }
        }
        __syncthreads();   // P plane + scaled accs ready

        // accs += P @ v
        {
            wmma::fragment<wmma::accumulator, 16, 16, 16, float> oacc[2];
#pragma unroll
            for (int i = 0; i < 2; i++)
                wmma::load_matrix_sync(oacc[i],
                                       accs + (wm * 32 + i * 16) * SLD + wn * 16,
                                       SLD, wmma::mem_row_major);
#pragma unroll
            for (int ks = 0; ks < 4; ks++) {
                wmma::fragment<wmma::matrix_b, 16, 16, 16, __half, wmma::row_major> bh;
                wmma::load_matrix_sync(bh, vh + (ks * 16) * AQLD + wn * 16, AQLD);
#pragma unroll
                for (int i = 0; i < 2; i++) {
                    wmma::fragment<wmma::matrix_a, 16, 16, 16, __half, wmma::row_major> ap;
                    wmma::load_matrix_sync(ap, ph + (wm * 32 + i * 16) * AQLD + ks * 16, AQLD);
                    wmma::mma_sync(oacc[i], ap, bh, oacc[i]);
                }
            }
#pragma unroll
            for (int i = 0; i < 2; i++)
                wmma::store_matrix_sync(accs + (wm * 32 + i * 16) * SLD + wn * 16,
                                        oacc[i], SLD, wmma::mem_row_major);
        }
    }
    __syncthreads();

    // out[b, q0+r, h*64 + c] = accs / l
#pragma unroll
    for (int p = 0; p < 4; p++) {
        int r = tr + p * 16;
        float inv = 1.0f / l_s[r];
        float4 ac = *(float4*)(accs + r * SLD + tc);
        ac.x *= inv; ac.y *= inv; ac.z *= inv; ac.w *= inv;
        size_t o = ((size_t)(b * SEQ + q0 + r)) * DMODEL + h * HDIM + tc;
        *(float4*)(out + o) = ac;
    }
}

// ============================================================================
// LayerNorm over D=1024. HALF=1: also emit fp16 plane (feeds GEMM).
// ============================================================================
template <int HALF>
__global__ __launch_bounds__(256)
void ln_kernel(const float* __restrict__ x, const float* __restrict__ gw,
               const float* __restrict__ bw, float* __restrict__ out,
               __half* __restrict__ oh)
{
    __shared__ float red[16];
    __shared__ float stats[2];
    const int row = blockIdx.x;
    const int tid = threadIdx.x;
    const float* xr = x + (size_t)row * DMODEL;

    float4 xv = *(const float4*)(xr + tid * 4);
    float s  = xv.x + xv.y + xv.z + xv.w;
    float s2 = xv.x * xv.x + xv.y * xv.y + xv.z * xv.z + xv.w * xv.w;
#pragma unroll
    for (int o = 16; o > 0; o >>= 1) {
        s  += __shfl_xor_sync(0xffffffffu, s, o);
        s2 += __shfl_xor_sync(0xffffffffu, s2, o);
    }
    if ((tid & 31) == 0) { red[tid >> 5] = s; red[8 + (tid >> 5)] = s2; }
    __syncthreads();
    if (tid == 0) {
        float ts = 0.f, ts2 = 0.f;
#pragma unroll
        for (int i = 0; i < 8; i++) { ts += red[i]; ts2 += red[8 + i]; }
        float mu  = ts * (1.0f / DMODEL);
        float var = ts2 * (1.0f / DMODEL) - mu * mu;
        stats[0] = mu;
        stats[1] = rsqrtf(var + 1e-5f);
    }
    __syncthreads();
    float mu = stats[0], rstd = stats[1];
    float4 gv = *(const float4*)(gw + tid * 4);
    float4 bv = *(const float4*)(bw + tid * 4);
    float4 ov;
    ov.x = (xv.x - mu) * rstd * gv.x + bv.x;
    ov.y = (xv.y - mu) * rstd * gv.y + bv.y;
    ov.z = (xv.z - mu) * rstd * gv.z + bv.z;
    ov.w = (xv.w - mu) * rstd * gv.w + bv.w;
    *(float4*)(out + (size_t)row * DMODEL + tid * 4) = ov;
    if constexpr (HALF == 1) {
        hi_store4(ov, oh + (size_t)row * DMODEL + tid * 4);
    }
}

// ============================================================================
extern "C" void kernel_launch(void* const* d_in, const int* in_sizes, int n_in,
                              void* d_out, int out_size)
{
    const float* src = (const float*)d_in[0];
    const float* wq  = (const float*)d_in[1];
    const float* bq  = (const float*)d_in[2];
    const float* wk  = (const float*)d_in[3];
    const float* bk  = (const float*)d_in[4];
    const float* wv  = (const float*)d_in[5];
    const float* bv  = (const float*)d_in[6];
    const float* w1  = (const float*)d_in[7];
    const float* b1  = (const float*)d_in[8];
    const float* w2  = (const float*)d_in[9];
    const float* b2  = (const float*)d_in[10];
    const float* g1  = (const float*)d_in[11];
    const float* be1 = (const float*)d_in[12];
    const float* g2  = (const float*)d_in[13];
    const float* be2 = (const float*)d_in[14];
    float* out = (float*)d_out;

    cudaFuncSetAttribute(gemm_h<0>, cudaFuncAttributeMaxDynamicSharedMemorySize, SPLIT_SMEM);
    cudaFuncSetAttribute(gemm_h<1>, cudaFuncAttributeMaxDynamicSharedMemorySize, SPLIT_SMEM);
    cudaFuncSetAttribute(gemm_h<2>, cudaFuncAttributeMaxDynamicSharedMemorySize, SPLIT_SMEM);
    cudaFuncSetAttribute(attn_kernel, cudaFuncAttributeMaxDynamicSharedMemorySize, ATTN_SMEM);

    float *attn, *xln, *y, *bqkv;
    __half *srch, *wqkvh, *w1h, *w2h, *xh, *hh, *qkvh;
    cudaGetSymbolAddress((void**)&attn, g_attn);
    cudaGetSymbolAddress((void**)&xln,  g_xln);
    cudaGetSymbolAddress((void**)&y,    g_y);
    cudaGetSymbolAddress((void**)&bqkv, g_bqkv);
    cudaGetSymbolAddress((void**)&srch, g_srch);
    cudaGetSymbolAddress((void**)&wqkvh, g_wqkvh);
    cudaGetSymbolAddress((void**)&w1h, g_w1h);
    cudaGetSymbolAddress((void**)&w2h, g_w2h);
    cudaGetSymbolAddress((void**)&xh,  g_xh);
    cudaGetSymbolAddress((void**)&hh,  g_hh);
    cudaGetSymbolAddress((void**)&qkvh, g_qkvh);

    // 0: fused prepass
    round_all<<<(RA_TOTAL + 255) / 256, 256>>>(src, wq, wk, wv, w1, w2, bq, bk, bv,
                                               srch, wqkvh, w1h, w2h, bqkv);

    // 1: fused QKV GEMM (N = 3072) -> q/k/v fp16 planes
    dim3 gQKV(3 * DMODEL / BN, MROWS / BM);        // (24, 128)
    gemm_h<0><<<gQKV, 256, SPLIT_SMEM>>>(srch, wqkvh, bqkv, nullptr,
                                         nullptr, qkvh, DMODEL, 3 * DMODEL);

    // 2: attention (plain fp16)
    attn_kernel<<<BATCH * NHEAD * (SEQ / 64), 256, ATTN_SMEM>>>(qkvh, attn);

    // 3: LN1 (fp32 + fp16 out)
    ln_kernel<1><<<MROWS, 256>>>(attn, g1, be1, xln, xh);

    // 4: FFN1 -> fp16 h
    dim3 gF1(DFF / BN, MROWS / BM);                // (32, 128)
    gemm_h<1><<<gF1, 256, SPLIT_SMEM>>>(xh, w1h, b1, nullptr,
                                        nullptr, hh, DMODEL, DFF);

    // 5: FFN2 (+residual)
    dim3 gF2(DMODEL / BN, MROWS / BM);             // (8, 128)
    gemm_h<2><<<gF2, 256, SPLIT_SMEM>>>(hh, w2h, b2, xln,
                                        y, nullptr, DFF, DMODEL);

    // 6: LN2 -> out
    ln_kernel<0><<<MROWS, 256>>>(y, g2, be2, out, nullptr);
}

// round 14
// speedup vs baseline: 2.4003x; 1.0083x over previous
#include <cuda_runtime.h>
#include <cuda_fp16.h>
#include <mma.h>
#include <cstdint>

using namespace nvcuda;

// Problem constants
#define BATCH  4
#define SEQ    4096
#define DMODEL 1024
#define NHEAD  16
#define HDIM   64
#define DFF    4096
#define WIN    512
#define MROWS  (BATCH*SEQ)          // 16384

// ---------------- scratch (device globals; no allocations allowed) ----------
static __device__ float g_attn[(size_t)MROWS * DMODEL];
static __device__ float g_xln [(size_t)MROWS * DMODEL];
static __device__ float g_y   [(size_t)MROWS * DMODEL];
// fp16 planes
static __device__ __align__(16) __half g_srch[(size_t)MROWS * DMODEL];
static __device__ __align__(16) __half g_wqkvh[(size_t)3 * DMODEL * DMODEL];
static __device__ __align__(16) __half g_w1h[(size_t)DFF * DMODEL];
static __device__ __align__(16) __half g_w2h[(size_t)DMODEL * DFF];
static __device__ __align__(16) __half g_xh [(size_t)MROWS * DMODEL];
static __device__ __align__(16) __half g_hh [(size_t)MROWS * DFF];
// q/k/v planes, [3][B,H,S,d]
static __device__ __align__(16) __half g_qkvh[(size_t)3 * MROWS * DMODEL];
static __device__ float g_bqkv[3 * DMODEL];

__device__ __forceinline__ void cp16(void* dst, const void* src) {
    unsigned int d = (unsigned int)__cvta_generic_to_shared(dst);
    asm volatile("cp.async.cg.shared.global [%0], [%1], 16;\n" :: "r"(d), "l"(src));
}

__device__ __forceinline__ void hi_store4(float4 x, __half* hp) {
    ((__half2*)hp)[0] = __floats2half2_rn(x.x, x.y);
    ((__half2*)hp)[1] = __floats2half2_rn(x.z, x.w);
}

// ============================================================================
// Fused prepass: src + weights -> fp16; bias pack fp32. float4-group indices.
// ============================================================================
#define RA_TOTAL 7078656
__global__ __launch_bounds__(256)
void round_all(const float* __restrict__ src,
               const float* __restrict__ wq, const float* __restrict__ wk,
               const float* __restrict__ wv, const float* __restrict__ w1,
               const float* __restrict__ w2, const float* __restrict__ bq,
               const float* __restrict__ bk, const float* __restrict__ bv,
               __half* __restrict__ srch, __half* __restrict__ wqkvh,
               __half* __restrict__ w1h, __half* __restrict__ w2h,
               float* __restrict__ bqkv)
{
    long long i = (long long)blockIdx.x * 256 + threadIdx.x;
    if (i >= RA_TOTAL) return;
    if (i >= 7077888) {                 // bias pack, fp32 copy
        long long j = i - 7077888;      // 0..767
        const float* in;
        float* op;
        if (j < 256)      { in = bq + j * 4;         op = bqkv + j * 4; }
        else if (j < 512) { in = bk + (j - 256) * 4; op = bqkv + 1024 + (j - 256) * 4; }
        else              { in = bv + (j - 512) * 4; op = bqkv + 2048 + (j - 512) * 4; }
        *(float4*)op = *(const float4*)in;
        return;
    }
    const float* in;
    __half* hp;
    if (i < 4194304)      { in = src + i * 4; hp = srch + i * 4; }
    else if (i < 4456448) { long long j = i - 4194304; in = wq + j * 4; hp = wqkvh + j * 4; }
    else if (i < 4718592) { long long j = i - 4456448; in = wk + j * 4; hp = wqkvh + 1048576 + j * 4; }
    else if (i < 4980736) { long long j = i - 4718592; in = wv + j * 4; hp = wqkvh + 2097152 + j * 4; }
    else if (i < 6029312) { long long j = i - 4980736; in = w1 + j * 4; hp = w1h + j * 4; }
    else                  { long long j = i - 6029312; in = w2 + j * 4; hp = w2h + j * 4; }
    hi_store4(*(const float4*)in, hp);
}

// ============================================================================
// Plain-fp16 TN GEMM: C = A @ W^T (fp32 accumulate)
// Block 128x128, BK=32, 256 thr = 8 warps as 4(m:32) x 2(n:64);
// warp tile 32x64, m16n16k16 wmma. SINGLE-sync mainloop: wait -> sync ->
// issue next-stage cp.async (overwrites buffer all warps finished 2 iters ago)
// -> compute.
//   MODE 0: +bias(packed), QKV scatter -> fp16 planes [3][B,H,S,d]
//   MODE 1: +bias, ReLU, fp16 out (FFN1)
//   MODE 2: +bias, +extra fp32 residual, fp32 out (FFN2)
// ============================================================================
#define BM 128
#define BN 128
#define BK 32
#define LDB 40                       // halfs per row (80B)
#define PLANE (128 * LDB)            // 5120 halfs
#define STG (2 * PLANE)              // A|W = 10240 halfs = 20480 B
#define SPLIT_SMEM 69632             // epilogue staging dominates (8*32*68*4)
#define QKV_PLANE ((size_t)MROWS * DMODEL)

template <int MODE>
__global__ __launch_bounds__(256, 2)
void gemm_h(const __half* __restrict__ Ah, const __half* __restrict__ Wh,
            const float* __restrict__ bias, const float* __restrict__ extra,
            float* __restrict__ out0, __half* __restrict__ oh,
            int K, int N)
{
    extern __shared__ __half smp[];
    const int tid = threadIdx.x;
    const int wid = tid >> 5;
    const int lane = tid & 31;
    const int wm = wid & 3;      // 0..3 (32-row strips)
    const int wn = wid >> 2;     // 0..1 (64-col strips)

    wmma::fragment<wmma::accumulator, 16, 16, 16, float> acc[2][4];
#pragma unroll
    for (int i = 0; i < 2; i++)
#pragma unroll
        for (int j = 0; j < 4; j++)
            wmma::fill_fragment(acc[i][j], 0.0f);

    const __half* Ahg = Ah + (size_t)blockIdx.y * BM * K;
    const __half* Whg = Wh + (size_t)blockIdx.x * BN * K;

    auto load_stage = [&](int s, int kt) {
        __half* st = smp + s * STG;
#pragma unroll
        for (int p = 0; p < 2; p++) {
            int c = tid + p * 256;            // 0..511
            int r = c >> 2, col = (c & 3) * 8;
            size_t go = (size_t)r * K + kt + col;
            unsigned so = r * LDB + col;
            cp16(st + so,         Ahg + go);
            cp16(st + PLANE + so, Whg + go);
        }
        asm volatile("cp.async.commit_group;\n");
    };

    const int T = K / BK;
    load_stage(0, 0);

    for (int t = 0; t < T; t++) {
        asm volatile("cp.async.wait_group 0;\n" ::: "memory");
        __syncthreads();   // stage-t visible to all; all warps done with t-1
        if (t + 1 < T) load_stage((t + 1) & 1, (t + 1) * BK);

        const __half* Ahs = smp + (t & 1) * STG;
        const __half* Bhs = Ahs + PLANE;

#pragma unroll
        for (int kk = 0; kk < BK; kk += 16) {
            wmma::fragment<wmma::matrix_a, 16, 16, 16, __half, wmma::row_major> ah[2];
#pragma unroll
            for (int i = 0; i < 2; i++)
                wmma::load_matrix_sync(ah[i], Ahs + (wm * 32 + i * 16) * LDB + kk, LDB);
#pragma unroll
            for (int j = 0; j < 4; j++) {
                wmma::fragment<wmma::matrix_b, 16, 16, 16, __half, wmma::col_major> bh;
                wmma::load_matrix_sync(bh, Bhs + (wn * 64 + j * 16) * LDB + kk, LDB);
#pragma unroll
                for (int i = 0; i < 2; i++)
                    wmma::mma_sync(acc[i][j], ah[i], bh, acc[i][j]);
            }
        }
    }
    __syncthreads();   // all compute done before epilogue aliases stage smem

    // Per-warp epilogue staging: 32x64 fp32 strip, stride 68.
    float* Cw = (float*)smp + wid * (32 * 68);
#pragma unroll
    for (int i = 0; i < 2; i++)
#pragma unroll
        for (int j = 0; j < 4; j++)
            wmma::store_matrix_sync(Cw + (i * 16) * 68 + j * 16, acc[i][j], 68,
                                    wmma::mem_row_major);
    __syncwarp();

    const int m = blockIdx.y * BM + wm * 32 + lane;
    const int n0 = blockIdx.x * BN + wn * 64;
    const float* crow = Cw + lane * 68;

#pragma unroll
    for (int c4 = 0; c4 < 16; c4++) {
        int n = n0 + c4 * 4;
        float4 c = *(float4*)(crow + c4 * 4);
        float4 bb = *(const float4*)(bias + n);
        c.x += bb.x; c.y += bb.y; c.z += bb.z; c.w += bb.w;
        if constexpr (MODE == 1) {
            c.x = fmaxf(c.x, 0.f); c.y = fmaxf(c.y, 0.f);
            c.z = fmaxf(c.z, 0.f); c.w = fmaxf(c.w, 0.f);
            hi_store4(c, oh + (size_t)m * N + n);
        } else if constexpr (MODE == 2) {
            float4 e = *(const float4*)(extra + (size_t)m * N + n);
            c.x += e.x; c.y += e.y; c.z += e.z; c.w += e.w;
            *(float4*)(out0 + (size_t)m * N + n) = c;
        } else {
            int mat = n >> 10;
            int nl  = n & 1023;
            int h   = nl >> 6;
            int dd  = nl & (HDIM - 1);
            int bi  = m >> 12;
            int s   = m & (SEQ - 1);
            size_t o = (((size_t)bi * NHEAD + h) * SEQ + s) * HDIM + dd;
            hi_store4(c, oh + mat * QKV_PLANE + o);
        }
    }
}

// ============================================================================
// Windowed causal flash attention, plain fp16 with base-2 softmax:
// sv = S * (0.125*log2e); p = exp2(sv - m) via h2exp2 (2 exps / MUFU op),
// f16x2 result stored directly as P. l accumulated in fp32.
// Block = (b,h,64-row q chunk), 256 thr, 8 warps as 2(m:32) x 4(n:16).
// ============================================================================
#define AQLD 72                     // halfs per row (144B)
#define APLANE (64 * AQLD)          // 4608 halfs
#define SLD 68                      // fp32 stride for S and acc
#define ATTN_SMEM (4 * APLANE * 2 + 2 * 64 * SLD * 4 + 2 * 64 * 4)  // 72192 B
#define SOFTMAX_SCALE 0.1803368801f  // 0.125 * log2(e)

__global__ __launch_bounds__(256, 2)
void attn_kernel(const __half* __restrict__ qkvh, float* __restrict__ out)
{
    const int idx = blockIdx.x;
    const int qc = idx & 7;
    const int w  = (idx >> 3) & 7;
    const int h  = (idx >> 6) & 15;
    const int b  = idx >> 10;

    extern __shared__ char smc[];
    __half* qh = (__half*)smc;
    __half* kh = qh + APLANE;
    __half* vh = qh + 2 * APLANE;
    __half* ph = qh + 3 * APLANE;
    float* s_s  = (float*)(smc + 4 * APLANE * 2);
    float* accs = s_s + 64 * SLD;
    float* m_s  = accs + 64 * SLD;
    float* l_s  = m_s + 64;

    const int tid = threadIdx.x;
    const int wid = tid >> 5;
    const int wm  = wid & 1;    // 0..1 (32-row strips)
    const int wn  = wid >> 1;   // 0..3 (16-col strips)
    const size_t NM = QKV_PLANE;
    const size_t headbase = ((size_t)(b * NHEAD + h)) * SEQ * HDIM;
    const int q0 = w * WIN + qc * 64;

    const int tr = tid >> 4;           // 0..15
    const int tc = (tid & 15) << 2;    // 0..60 step 4

    // load q plane (64 rows x 64 halfs = 512 8-half chunks)
    {
        const __half* qg = qkvh + headbase + (size_t)q0 * HDIM;
#pragma unroll
        for (int p = 0; p < 2; p++) {
            int c = tid + p * 256;          // 0..511
            int r = c >> 3, col = (c & 7) * 8;
            *(uint4*)(qh + r * AQLD + col) = *(const uint4*)(qg + (size_t)r * HDIM + col);
        }
    }
#pragma unroll
    for (int p = 0; p < 4; p++) {
        int r = tr + p * 16;
        *(float4*)(accs + r * SLD + tc) = make_float4(0.f, 0.f, 0.f, 0.f);
    }
    if (tid < 64) { m_s[tid] = -1e30f; l_s[tid] = 0.f; }

    const int kstart = (w == 0) ? 0 : (w - 1) * WIN;
    const int kend   = q0 + 64;

    const __half* kg = qkvh + NM + headbase;
    const __half* vg = qkvh + 2 * NM + headbase;

    for (int kc = kstart; kc < kend; kc += 64) {
        __syncthreads();   // prev PV complete before overwriting k/v planes

        // load kh/vh planes (2 x 512 chunks)
#pragma unroll
        for (int p = 0; p < 4; p++) {
            int c = tid + p * 256;          // 0..1023
            int plane = c >> 9;             // 0:kh 1:vh
            int cc = c & 511;
            int r = cc >> 3, col = (cc & 7) * 8;
            const __half* s = (plane ? vg : kg) + (size_t)(kc + r) * HDIM + col;
            __half* d = (plane ? vh : kh) + r * AQLD + col;
            *(uint4*)d = *(const uint4*)s;
        }
        __syncthreads();   // k/v ready

        // S = q @ k^T
        {
            wmma::fragment<wmma::accumulator, 16, 16, 16, float> sacc[2];
#pragma unroll
            for (int i = 0; i < 2; i++) wmma::fill_fragment(sacc[i], 0.0f);
#pragma unroll
            for (int ks = 0; ks < 4; ks++) {
                wmma::fragment<wmma::matrix_b, 16, 16, 16, __half, wmma::col_major> bh;
                wmma::load_matrix_sync(bh, kh + (wn * 16) * AQLD + ks * 16, AQLD);
#pragma unroll
                for (int i = 0; i < 2; i++) {
                    wmma::fragment<wmma::matrix_a, 16, 16, 16, __half, wmma::row_major> ah;
                    wmma::load_matrix_sync(ah, qh + (wm * 32 + i * 16) * AQLD + ks * 16, AQLD);
                    wmma::mma_sync(sacc[i], ah, bh, sacc[i]);
                }
            }
#pragma unroll
            for (int i = 0; i < 2; i++)
                wmma::store_matrix_sync(s_s + (wm * 32 + i * 16) * SLD + wn * 16,
                                        sacc[i], SLD, wmma::mem_row_major);
        }
        __syncthreads();   // scores ready

        // online softmax in base-2 domain; P via h2exp2, stored f16x2 direct
        {
            const bool diag = (kc == q0);
            const int r  = tid >> 2;           // 0..63
            const int c0 = (tid & 3) << 4;     // 0,16,32,48
            float* srow = s_s + r * SLD + c0;
            float sv[16];
            float mloc = -1e30f;
#pragma unroll
            for (int t = 0; t < 16; t++) {
                float x = srow[t] * SOFTMAX_SCALE;
                if (diag && (c0 + t > r)) x = -1e30f;
                sv[t] = x;
                mloc = fmaxf(mloc, x);
            }
            mloc = fmaxf(mloc, __shfl_xor_sync(0xffffffffu, mloc, 1));
            mloc = fmaxf(mloc, __shfl_xor_sync(0xffffffffu, mloc, 2));
            float mold = m_s[r];
            float mnew = fmaxf(mold, mloc);
            float ssum = 0.f;
#pragma unroll
            for (int t = 0; t < 16; t += 2) {
                __half2 hx = __floats2half2_rn(sv[t] - mnew, sv[t + 1] - mnew);
                __half2 pz = h2exp2(hx);
                *(__half2*)(ph + r * AQLD + c0 + t) = pz;
                float2 pf = __half22float2(pz);
                ssum += pf.x + pf.y;
            }
            ssum += __shfl_xor_sync(0xffffffffu, ssum, 1);
            ssum += __shfl_xor_sync(0xffffffffu, ssum, 2);
            float alpha = exp2f(mold - mnew);   // 0 on first chunk
            if ((tid & 3) == 0) {
                m_s[r] = mnew;
                l_s[r] = l_s[r] * alpha + ssum;
            }
            // rescale accumulator rows in-place
            float* arow = accs + r * SLD + c0;
#pragma unroll
            for (int t = 0; t < 4; t++) {
                float4 a4 = *(float4*)(arow + t * 4);
                a4.x *= alpha; a4.y *= alpha; a4.z *= alpha; a4.w *= alpha;
                *(float4*)(arow + t * 4) = a4;
            }
        }
        __syncthreads();   // P plane + scaled accs ready

        // accs += P @ v
        {
            wmma::fragment<wmma::accumulator, 16, 16, 16, float> oacc[2];
#pragma unroll
            for (int i = 0; i < 2; i++)
                wmma::load_matrix_sync(oacc[i],
                                       accs + (wm * 32 + i * 16) * SLD + wn * 16,
                                       SLD, wmma::mem_row_major);
#pragma unroll
            for (int ks = 0; ks < 4; ks++) {
                wmma::fragment<wmma::matrix_b, 16, 16, 16, __half, wmma::row_major> bh;
                wmma::load_matrix_sync(bh, vh + (ks * 16) * AQLD + wn * 16, AQLD);
#pragma unroll
                for (int i = 0; i < 2; i++) {
                    wmma::fragment<wmma::matrix_a, 16, 16, 16, __half, wmma::row_major> ap;
                    wmma::load_matrix_sync(ap, ph + (wm * 32 + i * 16) * AQLD + ks * 16, AQLD);
                    wmma::mma_sync(oacc[i], ap, bh, oacc[i]);
                }
            }
#pragma unroll
            for (int i = 0; i < 2; i++)
                wmma::store_matrix_sync(accs + (wm * 32 + i * 16) * SLD + wn * 16,
                                        oacc[i], SLD, wmma::mem_row_major);
        }
    }
    __syncthreads();

    // out[b, q0+r, h*64 + c] = accs / l
#pragma unroll
    for (int p = 0; p < 4; p++) {
        int r = tr + p * 16;
        float inv = 1.0f / l_s[r];
        float4 ac = *(float4*)(accs + r * SLD + tc);
        ac.x *= inv; ac.y *= inv; ac.z *= inv; ac.w *= inv;
        size_t o = ((size_t)(b * SEQ + q0 + r)) * DMODEL + h * HDIM + tc;
        *(float4*)(out + o) = ac;
    }
}

// ============================================================================
// LayerNorm over D=1024. HALF=1: also emit fp16 plane (feeds GEMM).
// ============================================================================
template <int HALF>
__global__ __launch_bounds__(256)
void ln_kernel(const float* __restrict__ x, const float* __restrict__ gw,
               const float* __restrict__ bw, float* __restrict__ out,
               __half* __restrict__ oh)
{
    __shared__ float red[16];
    __shared__ float stats[2];
    const int row = blockIdx.x;
    const int tid = threadIdx.x;
    const float* xr = x + (size_t)row * DMODEL;

    float4 xv = *(const float4*)(xr + tid * 4);
    float s  = xv.x + xv.y + xv.z + xv.w;
    float s2 = xv.x * xv.x + xv.y * xv.y + xv.z * xv.z + xv.w * xv.w;
#pragma unroll
    for (int o = 16; o > 0; o >>= 1) {
        s  += __shfl_xor_sync(0xffffffffu, s, o);
        s2 += __shfl_xor_sync(0xffffffffu, s2, o);
    }
    if ((tid & 31) == 0) { red[tid >> 5] = s; red[8 + (tid >> 5)] = s2; }
    __syncthreads();
    if (tid == 0) {
        float ts = 0.f, ts2 = 0.f;
#pragma unroll
        for (int i = 0; i < 8; i++) { ts += red[i]; ts2 += red[8 + i]; }
        float mu  = ts * (1.0f / DMODEL);
        float var = ts2 * (1.0f / DMODEL) - mu * mu;
        stats[0] = mu;
        stats[1] = rsqrtf(var + 1e-5f);
    }
    __syncthreads();
    float mu = stats[0], rstd = stats[1];
    float4 gv = *(const float4*)(gw + tid * 4);
    float4 bv = *(const float4*)(bw + tid * 4);
    float4 ov;
    ov.x = (xv.x - mu) * rstd * gv.x + bv.x;
    ov.y = (xv.y - mu) * rstd * gv.y + bv.y;
    ov.z = (xv.z - mu) * rstd * gv.z + bv.z;
    ov.w = (xv.w - mu) * rstd * gv.w + bv.w;
    *(float4*)(out + (size_t)row * DMODEL + tid * 4) = ov;
    if constexpr (HALF == 1) {
        hi_store4(ov, oh + (size_t)row * DMODEL + tid * 4);
    }
}

// ============================================================================
extern "C" void kernel_launch(void* const* d_in, const int* in_sizes, int n_in,
                              void* d_out, int out_size)
{
    const float* src = (const float*)d_in[0];
    const float* wq  = (const float*)d_in[1];
    const float* bq  = (const float*)d_in[2];
    const float* wk  = (const float*)d_in[3];
    const float* bk  = (const float*)d_in[4];
    const float* wv  = (const float*)d_in[5];
    const float* bv  = (const float*)d_in[6];
    const float* w1  = (const float*)d_in[7];
    const float* b1  = (const float*)d_in[8];
    const float* w2  = (const float*)d_in[9];
    const float* b2  = (const float*)d_in[10];
    const float* g1  = (const float*)d_in[11];
    const float* be1 = (const float*)d_in[12];
    const float* g2  = (const float*)d_in[13];
    const float* be2 = (const float*)d_in[14];
    float* out = (float*)d_out;

    cudaFuncSetAttribute(gemm_h<0>, cudaFuncAttributeMaxDynamicSharedMemorySize, SPLIT_SMEM);
    cudaFuncSetAttribute(gemm_h<1>, cudaFuncAttributeMaxDynamicSharedMemorySize, SPLIT_SMEM);
    cudaFuncSetAttribute(gemm_h<2>, cudaFuncAttributeMaxDynamicSharedMemorySize, SPLIT_SMEM);
    cudaFuncSetAttribute(attn_kernel, cudaFuncAttributeMaxDynamicSharedMemorySize, ATTN_SMEM);

    float *attn, *xln, *y, *bqkv;
    __half *srch, *wqkvh, *w1h, *w2h, *xh, *hh, *qkvh;
    cudaGetSymbolAddress((void**)&attn, g_attn);
    cudaGetSymbolAddress((void**)&xln,  g_xln);
    cudaGetSymbolAddress((void**)&y,    g_y);
    cudaGetSymbolAddress((void**)&bqkv, g_bqkv);
    cudaGetSymbolAddress((void**)&srch, g_srch);
    cudaGetSymbolAddress((void**)&wqkvh, g_wqkvh);
    cudaGetSymbolAddress((void**)&w1h, g_w1h);
    cudaGetSymbolAddress((void**)&w2h, g_w2h);
    cudaGetSymbolAddress((void**)&xh,  g_xh);
    cudaGetSymbolAddress((void**)&hh,  g_hh);
    cudaGetSymbolAddress((void**)&qkvh, g_qkvh);

    // 0: fused prepass
    round_all<<<(RA_TOTAL + 255) / 256, 256>>>(src, wq, wk, wv, w1, w2, bq, bk, bv,
                                               srch, wqkvh, w1h, w2h, bqkv);

    // 1: fused QKV GEMM (N = 3072) -> q/k/v fp16 planes
    dim3 gQKV(3 * DMODEL / BN, MROWS / BM);        // (24, 128)
    gemm_h<0><<<gQKV, 256, SPLIT_SMEM>>>(srch, wqkvh, bqkv, nullptr,
                                         nullptr, qkvh, DMODEL, 3 * DMODEL);

    // 2: attention (plain fp16, base-2 softmax)
    attn_kernel<<<BATCH * NHEAD * (SEQ / 64), 256, ATTN_SMEM>>>(qkvh, attn);

    // 3: LN1 (fp32 + fp16 out)
    ln_kernel<1><<<MROWS, 256>>>(attn, g1, be1, xln, xh);

    // 4: FFN1 -> fp16 h
    dim3 gF1(DFF / BN, MROWS / BM);                // (32, 128)
    gemm_h<1><<<gF1, 256, SPLIT_SMEM>>>(xh, w1h, b1, nullptr,
                                        nullptr, hh, DMODEL, DFF);

    // 5: FFN2 (+residual)
    dim3 gF2(DMODEL / BN, MROWS / BM);             // (8, 128)
    gemm_h<2><<<gF2, 256, SPLIT_SMEM>>>(hh, w2h, b2, xln,
                                        y, nullptr, DFF, DMODEL);

    // 6: LN2 -> out
    ln_kernel<0><<<MROWS, 256>>>(y, g2, be2, out, nullptr);
}

// round 15
// speedup vs baseline: 2.8150x; 1.1728x over previous
#include <cuda_runtime.h>
#include <cuda_fp16.h>
#include <mma.h>
#include <cstdint>

using namespace nvcuda;

// Problem constants
#define BATCH  4
#define SEQ    4096
#define DMODEL 1024
#define NHEAD  16
#define HDIM   64
#define DFF    4096
#define WIN    512
#define MROWS  (BATCH*SEQ)          // 16384

// ---------------- scratch (device globals; no allocations allowed) ----------
static __device__ float g_attn[(size_t)MROWS * DMODEL];
static __device__ float g_xln [(size_t)MROWS * DMODEL];
static __device__ float g_y   [(size_t)MROWS * DMODEL];
// fp16 planes
static __device__ __align__(16) __half g_srch[(size_t)MROWS * DMODEL];
static __device__ __align__(16) __half g_wqkvh[(size_t)3 * DMODEL * DMODEL];
static __device__ __align__(16) __half g_w1h[(size_t)DFF * DMODEL];
static __device__ __align__(16) __half g_w2h[(size_t)DMODEL * DFF];
static __device__ __align__(16) __half g_xh [(size_t)MROWS * DMODEL];
static __device__ __align__(16) __half g_hh [(size_t)MROWS * DFF];
// q/k/v planes, [3][B,H,S,d]
static __device__ __align__(16) __half g_qkvh[(size_t)3 * MROWS * DMODEL];
static __device__ float g_bqkv[3 * DMODEL];

__device__ __forceinline__ void cp16(void* dst, const void* src) {
    unsigned int d = (unsigned int)__cvta_generic_to_shared(dst);
    asm volatile("cp.async.cg.shared.global [%0], [%1], 16;\n" :: "r"(d), "l"(src));
}
__device__ __forceinline__ void cp16s(unsigned dst, const void* src) {
    asm volatile("cp.async.cg.shared.global [%0], [%1], 16;\n" :: "r"(dst), "l"(src));
}

__device__ __forceinline__ void hi_store4(float4 x, __half* hp) {
    ((__half2*)hp)[0] = __floats2half2_rn(x.x, x.y);
    ((__half2*)hp)[1] = __floats2half2_rn(x.z, x.w);
}

__device__ __forceinline__ void ldsm4(unsigned* r, unsigned a) {
    asm volatile("ldmatrix.sync.aligned.m8n8.x4.shared.b16 {%0,%1,%2,%3}, [%4];"
                 : "=r"(r[0]), "=r"(r[1]), "=r"(r[2]), "=r"(r[3]) : "r"(a));
}
__device__ __forceinline__ void ldsm4t(unsigned* r, unsigned a) {
    asm volatile("ldmatrix.sync.aligned.m8n8.x4.trans.shared.b16 {%0,%1,%2,%3}, [%4];"
                 : "=r"(r[0]), "=r"(r[1]), "=r"(r[2]), "=r"(r[3]) : "r"(a));
}
__device__ __forceinline__ void mma16816(float* c, const unsigned* a, const unsigned* b) {
    asm volatile("mma.sync.aligned.m16n8k16.row.col.f32.f16.f16.f32 "
                 "{%0,%1,%2,%3}, {%4,%5,%6,%7}, {%8,%9}, {%0,%1,%2,%3};"
                 : "+f"(c[0]), "+f"(c[1]), "+f"(c[2]), "+f"(c[3])
                 : "r"(a[0]), "r"(a[1]), "r"(a[2]), "r"(a[3]), "r"(b[0]), "r"(b[1]));
}

// ============================================================================
// Fused prepass: src + weights -> fp16; bias pack fp32. float4-group indices.
// ============================================================================
#define RA_TOTAL 7078656
__global__ __launch_bounds__(256)
void round_all(const float* __restrict__ src,
               const float* __restrict__ wq, const float* __restrict__ wk,
               const float* __restrict__ wv, const float* __restrict__ w1,
               const float* __restrict__ w2, const float* __restrict__ bq,
               const float* __restrict__ bk, const float* __restrict__ bv,
               __half* __restrict__ srch, __half* __restrict__ wqkvh,
               __half* __restrict__ w1h, __half* __restrict__ w2h,
               float* __restrict__ bqkv)
{
    long long i = (long long)blockIdx.x * 256 + threadIdx.x;
    if (i >= RA_TOTAL) return;
    if (i >= 7077888) {                 // bias pack, fp32 copy
        long long j = i - 7077888;      // 0..767
        const float* in;
        float* op;
        if (j < 256)      { in = bq + j * 4;         op = bqkv + j * 4; }
        else if (j < 512) { in = bk + (j - 256) * 4; op = bqkv + 1024 + (j - 256) * 4; }
        else              { in = bv + (j - 512) * 4; op = bqkv + 2048 + (j - 512) * 4; }
        *(float4*)op = *(const float4*)in;
        return;
    }
    const float* in;
    __half* hp;
    if (i < 4194304)      { in = src + i * 4; hp = srch + i * 4; }
    else if (i < 4456448) { long long j = i - 4194304; in = wq + j * 4; hp = wqkvh + j * 4; }
    else if (i < 4718592) { long long j = i - 4456448; in = wk + j * 4; hp = wqkvh + 1048576 + j * 4; }
    else if (i < 4980736) { long long j = i - 4718592; in = wv + j * 4; hp = wqkvh + 2097152 + j * 4; }
    else if (i < 6029312) { long long j = i - 4980736; in = w1 + j * 4; hp = w1h + j * 4; }
    else                  { long long j = i - 6029312; in = w2 + j * 4; hp = w2h + j * 4; }
    hi_store4(*(const float4*)in, hp);
}

// ============================================================================
// Plain-fp16 TN GEMM (unchanged from R14): single-sync cp.async mainloop.
// ============================================================================
#define BM 128
#define BN 128
#define BK 32
#define LDB 40
#define PLANE (128 * LDB)
#define STG (2 * PLANE)
#define SPLIT_SMEM 69632
#define QKV_PLANE ((size_t)MROWS * DMODEL)

template <int MODE>
__global__ __launch_bounds__(256, 2)
void gemm_h(const __half* __restrict__ Ah, const __half* __restrict__ Wh,
            const float* __restrict__ bias, const float* __restrict__ extra,
            float* __restrict__ out0, __half* __restrict__ oh,
            int K, int N)
{
    extern __shared__ __half smp[];
    const int tid = threadIdx.x;
    const int wid = tid >> 5;
    const int lane = tid & 31;
    const int wm = wid & 3;
    const int wn = wid >> 2;

    wmma::fragment<wmma::accumulator, 16, 16, 16, float> acc[2][4];
#pragma unroll
    for (int i = 0; i < 2; i++)
#pragma unroll
        for (int j = 0; j < 4; j++)
            wmma::fill_fragment(acc[i][j], 0.0f);

    const __half* Ahg = Ah + (size_t)blockIdx.y * BM * K;
    const __half* Whg = Wh + (size_t)blockIdx.x * BN * K;

    auto load_stage = [&](int s, int kt) {
        __half* st = smp + s * STG;
#pragma unroll
        for (int p = 0; p < 2; p++) {
            int c = tid + p * 256;
            int r = c >> 2, col = (c & 3) * 8;
            size_t go = (size_t)r * K + kt + col;
            unsigned so = r * LDB + col;
            cp16(st + so,         Ahg + go);
            cp16(st + PLANE + so, Whg + go);
        }
        asm volatile("cp.async.commit_group;\n");
    };

    const int T = K / BK;
    load_stage(0, 0);

    for (int t = 0; t < T; t++) {
        asm volatile("cp.async.wait_group 0;\n" ::: "memory");
        __syncthreads();
        if (t + 1 < T) load_stage((t + 1) & 1, (t + 1) * BK);

        const __half* Ahs = smp + (t & 1) * STG;
        const __half* Bhs = Ahs + PLANE;

#pragma unroll
        for (int kk = 0; kk < BK; kk += 16) {
            wmma::fragment<wmma::matrix_a, 16, 16, 16, __half, wmma::row_major> ah[2];
#pragma unroll
            for (int i = 0; i < 2; i++)
                wmma::load_matrix_sync(ah[i], Ahs + (wm * 32 + i * 16) * LDB + kk, LDB);
#pragma unroll
            for (int j = 0; j < 4; j++) {
                wmma::fragment<wmma::matrix_b, 16, 16, 16, __half, wmma::col_major> bh;
                wmma::load_matrix_sync(bh, Bhs + (wn * 64 + j * 16) * LDB + kk, LDB);
#pragma unroll
                for (int i = 0; i < 2; i++)
                    wmma::mma_sync(acc[i][j], ah[i], bh, acc[i][j]);
            }
        }
    }
    __syncthreads();

    float* Cw = (float*)smp + wid * (32 * 68);
#pragma unroll
    for (int i = 0; i < 2; i++)
#pragma unroll
        for (int j = 0; j < 4; j++)
            wmma::store_matrix_sync(Cw + (i * 16) * 68 + j * 16, acc[i][j], 68,
                                    wmma::mem_row_major);
    __syncwarp();

    const int m = blockIdx.y * BM + wm * 32 + lane;
    const int n0 = blockIdx.x * BN + wn * 64;
    const float* crow = Cw + lane * 68;

#pragma unroll
    for (int c4 = 0; c4 < 16; c4++) {
        int n = n0 + c4 * 4;
        float4 c = *(float4*)(crow + c4 * 4);
        float4 bb = *(const float4*)(bias + n);
        c.x += bb.x; c.y += bb.y; c.z += bb.z; c.w += bb.w;
        if constexpr (MODE == 1) {
            c.x = fmaxf(c.x, 0.f); c.y = fmaxf(c.y, 0.f);
            c.z = fmaxf(c.z, 0.f); c.w = fmaxf(c.w, 0.f);
            hi_store4(c, oh + (size_t)m * N + n);
        } else if constexpr (MODE == 2) {
            float4 e = *(const float4*)(extra + (size_t)m * N + n);
            c.x += e.x; c.y += e.y; c.z += e.z; c.w += e.w;
            *(float4*)(out0 + (size_t)m * N + n) = c;
        } else {
            int mat = n >> 10;
            int nl  = n & 1023;
            int h   = nl >> 6;
            int dd  = nl & (HDIM - 1);
            int bi  = m >> 12;
            int s   = m & (SEQ - 1);
            size_t o = (((size_t)bi * NHEAD + h) * SEQ + s) * HDIM + dd;
            hi_store4(c, oh + mat * QKV_PLANE + o);
        }
    }
}

// ============================================================================
// FlashAttention-2 style register-resident attention (mma.sync.m16n8k16):
// CTA = 128 q-rows of one (b,h); 8 warps x 16 rows. S/P/O in registers;
// k/v double-buffered cp.async; 1 __syncthreads per 64-key chunk.
// Base-2 softmax, exp via h2exp2; P = S C-frags repacked (no smem).
// ============================================================================
#define AQLD 72                     // halfs per smem row (144B)
#define APLANE (64 * AQLD)          // 4608 halfs
#define ATTN_SMEM (4 * APLANE * 2)  // 36864 B (2 stages x (k|v))
#define SOFTMAX_SCALE 0.1803368801f  // 0.125 * log2(e)

__global__ __launch_bounds__(256, 2)
void attn_kernel(const __half* __restrict__ qkvh, float* __restrict__ out)
{
    const int idx = blockIdx.x;        // 2048 = b(4) x h(16) x qc(32)
    const int qc = idx & 31;
    const int h  = (idx >> 5) & 15;
    const int b  = idx >> 9;
    const int q0 = qc * 128;
    const int w  = qc >> 2;            // 512-window index

    extern __shared__ char smc[];
    const unsigned smb = (unsigned)__cvta_generic_to_shared(smc);

    const int tid = threadIdx.x;
    const int wid = tid >> 5;
    const int lane = tid & 31;
    const size_t headbase = ((size_t)(b * NHEAD + h)) * SEQ * HDIM;

    const __half* qg = qkvh + headbase + (size_t)q0 * HDIM;
    const __half* kg = qkvh + QKV_PLANE + headbase;
    const __half* vg = qkvh + 2 * QKV_PLANE + headbase;

    // ---- load Q 128x64 into smem (contiguous across stage-0 k|v planes) ----
#pragma unroll
    for (int p = 0; p < 4; p++) {
        int c = tid + p * 256;          // 0..1023
        int r = c >> 3, col = (c & 7) * 8;
        cp16s(smb + (r * AQLD + col) * 2, qg + (size_t)r * HDIM + col);
    }
    asm volatile("cp.async.commit_group;\n");
    asm volatile("cp.async.wait_group 0;\n" ::: "memory");
    __syncthreads();

    // Q A-fragments (4 k-steps), kept in registers for the whole kernel
    unsigned qf[4][4];
    {
        unsigned qaddr = smb +
            (((unsigned)(wid * 16 + (lane & 7) + ((lane >> 3) & 1) * 8)) * AQLD
             + (lane >> 4) * 8) * 2;
#pragma unroll
        for (int kt = 0; kt < 4; kt++)
            ldsm4(qf[kt], qaddr + kt * 16 * 2);
    }
    __syncthreads();   // Q reads done before k/v overwrite stage 0

    float o[8][4];
#pragma unroll
    for (int nt = 0; nt < 8; nt++) { o[nt][0] = o[nt][1] = o[nt][2] = o[nt][3] = 0.f; }
    float m0 = -1e30f, m1 = -1e30f, l0 = 0.f, l1 = 0.f;

    const int kstart = (w == 0) ? 0 : (w - 1) * WIN;
    const int kend   = q0 + 128;
    const int nch    = (kend - kstart) >> 6;

    // per-thread ldmatrix address offsets (within a stage's k or v plane)
    const unsigned kaoff = (((unsigned)(lane & 7)) * AQLD + (lane >> 3) * 8) * 2;
    const unsigned vaoff = ((((unsigned)(lane & 7)) + ((lane >> 3) & 1) * 8) * AQLD
                            + (lane >> 4) * 8) * 2;
    const int rbase = q0 + wid * 16;

    auto load_kv = [&](int st, int kc) {
#pragma unroll
        for (int p = 0; p < 4; p++) {
            int c = tid + p * 256;          // 0..1023
            int plane = c >> 9;             // 0:k 1:v
            int cc = c & 511;
            int r = cc >> 3, col = (cc & 7) * 8;
            const __half* s = (plane ? vg : kg) + (size_t)(kc + r) * HDIM + col;
            cp16s(smb + (st * 2 * APLANE + plane * APLANE + r * AQLD + col) * 2, s);
        }
        asm volatile("cp.async.commit_group;\n");
    };

    load_kv(0, kstart);

    for (int ci = 0; ci < nch; ci++) {
        const int kc = kstart + ci * 64;
        const int st = ci & 1;
        asm volatile("cp.async.wait_group 0;\n" ::: "memory");
        __syncthreads();
        if (ci + 1 < nch) load_kv(st ^ 1, kc + 64);

        const unsigned kb = smb + (st * 2 * APLANE) * 2;
        const unsigned vb = kb + APLANE * 2;

        // ---- S = q @ k^T : 8 n-tiles x 4 k-steps ----
        float s[8][4];
#pragma unroll
        for (int nt = 0; nt < 8; nt++) {
            s[nt][0] = s[nt][1] = s[nt][2] = s[nt][3] = 0.f;
#pragma unroll
            for (int ktp = 0; ktp < 2; ktp++) {
                unsigned kf[4];
                ldsm4(kf, kb + (8 * nt) * AQLD * 2 + ktp * 32 * 2 + kaoff);
                mma16816(s[nt], qf[2 * ktp],     kf);
                mma16816(s[nt], qf[2 * ktp + 1], kf + 2);
            }
        }

        // ---- softmax (base-2, in registers) ----
        {
            const bool need_mask = (kc + 63 > rbase);
            const int r0g = rbase + (lane >> 2);
            const int r1g = r0g + 8;
            float mloc0 = -1e30f, mloc1 = -1e30f;
#pragma unroll
            for (int nt = 0; nt < 8; nt++) {
                int cg = kc + nt * 8 + (lane & 3) * 2;
                float x0 = s[nt][0] * SOFTMAX_SCALE;
                float x1 = s[nt][1] * SOFTMAX_SCALE;
                float x2 = s[nt][2] * SOFTMAX_SCALE;
                float x3 = s[nt][3] * SOFTMAX_SCALE;
                if (need_mask) {
                    if (cg     > r0g) x0 = -1e30f;
                    if (cg + 1 > r0g) x1 = -1e30f;
                    if (cg     > r1g) x2 = -1e30f;
                    if (cg + 1 > r1g) x3 = -1e30f;
                }
                s[nt][0] = x0; s[nt][1] = x1; s[nt][2] = x2; s[nt][3] = x3;
                mloc0 = fmaxf(mloc0, fmaxf(x0, x1));
                mloc1 = fmaxf(mloc1, fmaxf(x2, x3));
            }
            mloc0 = fmaxf(mloc0, __shfl_xor_sync(0xffffffffu, mloc0, 1));
            mloc0 = fmaxf(mloc0, __shfl_xor_sync(0xffffffffu, mloc0, 2));
            mloc1 = fmaxf(mloc1, __shfl_xor_sync(0xffffffffu, mloc1, 1));
            mloc1 = fmaxf(mloc1, __shfl_xor_sync(0xffffffffu, mloc1, 2));
            float mn0 = fmaxf(m0, mloc0);
            float mn1 = fmaxf(m1, mloc1);
            float al0 = exp2f(m0 - mn0);
            float al1 = exp2f(m1 - mn1);
            m0 = mn0; m1 = mn1;

            // P fragments (f16x2) + row sums
            unsigned pf[4][4];
            float ss0 = 0.f, ss1 = 0.f;
#pragma unroll
            for (int nt = 0; nt < 8; nt++) {
                __half2 pz0 = h2exp2(__floats2half2_rn(s[nt][0] - mn0, s[nt][1] - mn0));
                __half2 pz1 = h2exp2(__floats2half2_rn(s[nt][2] - mn1, s[nt][3] - mn1));
                float2 f0 = __half22float2(pz0);
                float2 f1 = __half22float2(pz1);
                ss0 += f0.x + f0.y;
                ss1 += f1.x + f1.y;
                pf[nt >> 1][(nt & 1) * 2]     = *(unsigned*)&pz0;
                pf[nt >> 1][(nt & 1) * 2 + 1] = *(unsigned*)&pz1;
            }
            ss0 += __shfl_xor_sync(0xffffffffu, ss0, 1);
            ss0 += __shfl_xor_sync(0xffffffffu, ss0, 2);
            ss1 += __shfl_xor_sync(0xffffffffu, ss1, 1);
            ss1 += __shfl_xor_sync(0xffffffffu, ss1, 2);
            l0 = l0 * al0 + ss0;
            l1 = l1 * al1 + ss1;

            // rescale O
#pragma unroll
            for (int nt = 0; nt < 8; nt++) {
                o[nt][0] *= al0; o[nt][1] *= al0;
                o[nt][2] *= al1; o[nt][3] *= al1;
            }

            // ---- O += P @ v : 4 dim-tile-pairs x 4 k-steps ----
#pragma unroll
            for (int ndp = 0; ndp < 4; ndp++) {
#pragma unroll
                for (int kt = 0; kt < 4; kt++) {
                    unsigned vf[4];
                    ldsm4t(vf, vb + (kt * 16) * AQLD * 2 + (2 * ndp) * 8 * 2 + vaoff);
                    mma16816(o[2 * ndp],     pf[kt], vf);
                    mma16816(o[2 * ndp + 1], pf[kt], vf + 2);
                }
            }
        }
    }

    // ---- epilogue: out[b, row, h*64+col] = o / l ----
    const float inv0 = 1.0f / l0;
    const float inv1 = 1.0f / l1;
    const int r0 = q0 + wid * 16 + (lane >> 2);
    const int r1 = r0 + 8;
    const int cbase = h * HDIM + (lane & 3) * 2;
#pragma unroll
    for (int nt = 0; nt < 8; nt++) {
        int col = cbase + nt * 8;
        float2 v0 = make_float2(o[nt][0] * inv0, o[nt][1] * inv0);
        float2 v1 = make_float2(o[nt][2] * inv1, o[nt][3] * inv1);
        *(float2*)(out + ((size_t)(b * SEQ + r0)) * DMODEL + col) = v0;
        *(float2*)(out + ((size_t)(b * SEQ + r1)) * DMODEL + col) = v1;
    }
}

// ============================================================================
// LayerNorm over D=1024. HALF=1: also emit fp16 plane (feeds GEMM).
// ============================================================================
template <int HALF>
__global__ __launch_bounds__(256)
void ln_kernel(const float* __restrict__ x, const float* __restrict__ gw,
               const float* __restrict__ bw, float* __restrict__ out,
               __half* __restrict__ oh)
{
    __shared__ float red[16];
    __shared__ float stats[2];
    const int row = blockIdx.x;
    const int tid = threadIdx.x;
    const float* xr = x + (size_t)row * DMODEL;

    float4 xv = *(const float4*)(xr + tid * 4);
    float s  = xv.x + xv.y + xv.z + xv.w;
    float s2 = xv.x * xv.x + xv.y * xv.y + xv.z * xv.z + xv.w * xv.w;
#pragma unroll
    for (int o = 16; o > 0; o >>= 1) {
        s  += __shfl_xor_sync(0xffffffffu, s, o);
        s2 += __shfl_xor_sync(0xffffffffu, s2, o);
    }
    if ((tid & 31) == 0) { red[tid >> 5] = s; red[8 + (tid >> 5)] = s2; }
    __syncthreads();
    if (tid == 0) {
        float ts = 0.f, ts2 = 0.f;
#pragma unroll
        for (int i = 0; i < 8; i++) { ts += red[i]; ts2 += red[8 + i]; }
        float mu  = ts * (1.0f / DMODEL);
        float var = ts2 * (1.0f / DMODEL) - mu * mu;
        stats[0] = mu;
        stats[1] = rsqrtf(var + 1e-5f);
    }
    __syncthreads();
    float mu = stats[0], rstd = stats[1];
    float4 gv = *(const float4*)(gw + tid * 4);
    float4 bv = *(const float4*)(bw + tid * 4);
    float4 ov;
    ov.x = (xv.x - mu) * rstd * gv.x + bv.x;
    ov.y = (xv.y - mu) * rstd * gv.y + bv.y;
    ov.z = (xv.z - mu) * rstd * gv.z + bv.z;
    ov.w = (xv.w - mu) * rstd * gv.w + bv.w;
    *(float4*)(out + (size_t)row * DMODEL + tid * 4) = ov;
    if constexpr (HALF == 1) {
        hi_store4(ov, oh + (size_t)row * DMODEL + tid * 4);
    }
}

// ============================================================================
extern "C" void kernel_launch(void* const* d_in, const int* in_sizes, int n_in,
                              void* d_out, int out_size)
{
    const float* src = (const float*)d_in[0];
    const float* wq  = (const float*)d_in[1];
    const float* bq  = (const float*)d_in[2];
    const float* wk  = (const float*)d_in[3];
    const float* bk  = (const float*)d_in[4];
    const float* wv  = (const float*)d_in[5];
    const float* bv  = (const float*)d_in[6];
    const float* w1  = (const float*)d_in[7];
    const float* b1  = (const float*)d_in[8];
    const float* w2  = (const float*)d_in[9];
    const float* b2  = (const float*)d_in[10];
    const float* g1  = (const float*)d_in[11];
    const float* be1 = (const float*)d_in[12];
    const float* g2  = (const float*)d_in[13];
    const float* be2 = (const float*)d_in[14];
    float* out = (float*)d_out;

    cudaFuncSetAttribute(gemm_h<0>, cudaFuncAttributeMaxDynamicSharedMemorySize, SPLIT_SMEM);
    cudaFuncSetAttribute(gemm_h<1>, cudaFuncAttributeMaxDynamicSharedMemorySize, SPLIT_SMEM);
    cudaFuncSetAttribute(gemm_h<2>, cudaFuncAttributeMaxDynamicSharedMemorySize, SPLIT_SMEM);
    cudaFuncSetAttribute(attn_kernel, cudaFuncAttributeMaxDynamicSharedMemorySize, ATTN_SMEM);

    float *attn, *xln, *y, *bqkv;
    __half *srch, *wqkvh, *w1h, *w2h, *xh, *hh, *qkvh;
    cudaGetSymbolAddress((void**)&attn, g_attn);
    cudaGetSymbolAddress((void**)&xln,  g_xln);
    cudaGetSymbolAddress((void**)&y,    g_y);
    cudaGetSymbolAddress((void**)&bqkv, g_bqkv);
    cudaGetSymbolAddress((void**)&srch, g_srch);
    cudaGetSymbolAddress((void**)&wqkvh, g_wqkvh);
    cudaGetSymbolAddress((void**)&w1h, g_w1h);
    cudaGetSymbolAddress((void**)&w2h, g_w2h);
    cudaGetSymbolAddress((void**)&xh,  g_xh);
    cudaGetSymbolAddress((void**)&hh,  g_hh);
    cudaGetSymbolAddress((void**)&qkvh, g_qkvh);

    // 0: fused prepass
    round_all<<<(RA_TOTAL + 255) / 256, 256>>>(src, wq, wk, wv, w1, w2, bq, bk, bv,
                                               srch, wqkvh, w1h, w2h, bqkv);

    // 1: fused QKV GEMM (N = 3072) -> q/k/v fp16 planes
    dim3 gQKV(3 * DMODEL / BN, MROWS / BM);        // (24, 128)
    gemm_h<0><<<gQKV, 256, SPLIT_SMEM>>>(srch, wqkvh, bqkv, nullptr,
                                         nullptr, qkvh, DMODEL, 3 * DMODEL);

    // 2: attention (FA2-style register-resident)
    attn_kernel<<<BATCH * NHEAD * (SEQ / 128), 256, ATTN_SMEM>>>(qkvh, attn);

    // 3: LN1 (fp32 + fp16 out)
    ln_kernel<1><<<MROWS, 256>>>(attn, g1, be1, xln, xh);

    // 4: FFN1 -> fp16 h
    dim3 gF1(DFF / BN, MROWS / BM);                // (32, 128)
    gemm_h<1><<<gF1, 256, SPLIT_SMEM>>>(xh, w1h, b1, nullptr,
                                        nullptr, hh, DMODEL, DFF);

    // 5: FFN2 (+residual)
    dim3 gF2(DMODEL / BN, MROWS / BM);             // (8, 128)
    gemm_h<2><<<gF2, 256, SPLIT_SMEM>>>(hh, w2h, b2, xln,
                                        y, nullptr, DFF, DMODEL);

    // 6: LN2 -> out
    ln_kernel<0><<<MROWS, 256>>>(y, g2, be2, out, nullptr);
}